// round 11
// baseline (speedup 1.0000x reference)
#include <cuda_runtime.h>
#include <cstdint>
#include <math.h>

#define NRAY 4096
#define NPTS 196608   /* NRAY * 48 */

/* output offsets (floats) */
#define OFF_RGB   0
#define OFF_DEPTH 131072
#define OFF_WSUM  135168
#define OFF_GRAD  139264
#define OFF_GC    151552
#define OFF_SDF   1331200

/* scratch */
__device__ float    g_tp  [2*3*256*256*32]; /* [b][p][y][x][c] */
__device__ float    g_dep [NRAY*96];
__device__ float    g_dens[NRAY*96];
__device__ float    g_rgb [NRAY*96*32];
__device__ float    g_gn  [NRAY*96*3];
__device__ float    g_w   [NRAY*95];
__device__ int      g_ord [NRAY*96];
__device__ unsigned g_dminU, g_dmaxU;

/* ---------------- Threefry2x32-20 (JAX partitionable) ---------------- */
__host__ __device__ inline unsigned rotl32(unsigned v, int r){ return (v<<r)|(v>>(32-r)); }

__host__ __device__ inline void tf2x32(unsigned k0, unsigned k1, unsigned x0, unsigned x1,
                                       unsigned &o0, unsigned &o1){
    unsigned k2 = k0 ^ k1 ^ 0x1BD11BDAu;
    x0 += k0; x1 += k1;
#define TF_R(r) { x0 += x1; x1 = rotl32(x1,(r)); x1 ^= x0; }
    TF_R(13) TF_R(15) TF_R(26) TF_R(6)
    x0 += k1; x1 += k2 + 1u;
    TF_R(17) TF_R(29) TF_R(16) TF_R(24)
    x0 += k2; x1 += k0 + 2u;
    TF_R(13) TF_R(15) TF_R(26) TF_R(6)
    x0 += k0; x1 += k1 + 3u;
    TF_R(17) TF_R(29) TF_R(16) TF_R(24)
    x0 += k1; x1 += k2 + 4u;
    TF_R(13) TF_R(15) TF_R(26) TF_R(6)
    x0 += k2; x1 += k0 + 5u;
#undef TF_R
    o0 = x0; o1 = x1;
}

__device__ inline float uniform01(unsigned k0, unsigned k1, unsigned idx){
    unsigned a, b;
    tf2x32(k0, k1, 0u, idx, a, b);
    unsigned bits = a ^ b;
    unsigned fb = (bits >> 9) | 0x3F800000u;
    float f = __fadd_rn(__uint_as_float(fb), -1.0f);
    return fmaxf(0.0f, f);
}

/* ---------------- XLA:CPU math replicas (llvm_ir_runtime / Cephes) ---------------- */
/* exp: Cephes two-constant Cody-Waite, FMA-contracted, clamp, floor(x*log2e+0.5) */
__device__ inline float xla_expf(float x){
    float cx = fminf(fmaxf(x, -88.3762626647949f), 88.3762626647950f);
    float fx = floorf(fmaf(cx, 1.44269504088896341f, 0.5f));
    float r = fmaf(-0.693359375f, fx, cx);       /* x - fx*C1 */
    r = fmaf(2.12194440e-4f, fx, r);             /* x - fx*C1 - fx*C2, C2=-2.12194440e-4 */
    float z = __fmul_rn(r, r);
    float y = 1.9875691500e-4f;
    y = fmaf(y, r, 1.3981999507e-3f);
    y = fmaf(y, r, 8.3334519073e-3f);
    y = fmaf(y, r, 4.1665795894e-2f);
    y = fmaf(y, r, 1.6666665459e-1f);
    y = fmaf(y, r, 5.0000001201e-1f);
    y = fmaf(y, z, r);
    y = __fadd_rn(1.0f, y);
    int n = (int)fx;
    float s = __uint_as_float((unsigned)((n + 127) << 23));
    return __fmul_rn(y, s);
}

/* log: Cephes 9-term (inputs here are positive, normal) */
__device__ inline float xla_logf(float u){
    unsigned iu = __float_as_uint(u);
    int e = (int)(iu >> 23) - 126;
    float m = __uint_as_float((iu & 0x007FFFFFu) | 0x3F000000u); /* [0.5,1) */
    float x;
    if (m < 0.707106781186547524f){ e -= 1; x = __fadd_rn(__fadd_rn(m, -1.0f), m); }
    else                          { x = __fadd_rn(m, -1.0f); }
    float z = __fmul_rn(x, x);
    float y = 7.0376836292e-2f;
    y = fmaf(y, x, -1.1514610310e-1f);
    y = fmaf(y, x,  1.1676998740e-1f);
    y = fmaf(y, x, -1.2420140846e-1f);
    y = fmaf(y, x,  1.4249322787e-1f);
    y = fmaf(y, x, -1.6668057665e-1f);
    y = fmaf(y, x,  2.0000714765e-1f);
    y = fmaf(y, x, -2.4999993993e-1f);
    y = fmaf(y, x,  3.3333331174e-1f);
    y = __fmul_rn(__fmul_rn(y, x), z);
    float ef = (float)e;
    y = fmaf(ef, -2.12194440e-4f, y);
    y = fmaf(z, -0.5f, y);
    x = __fadd_rn(x, y);
    x = fmaf(ef, 0.693359375f, x);
    return x;
}

/* log1p: XLA EmitLog1p — |x|<1e-4 ? x*(1-0.5x) : log(1+x) */
__device__ inline float xla_log1pf(float x){
    float large_ = xla_logf(__fadd_rn(x, 1.0f));
    float small_ = __fmul_rn(fmaf(-0.5f, x, 1.0f), x);
    return (fabsf(x) < 1e-4f) ? small_ : large_;
}

/* tanh: XLA/Eigen rational polynomial */
__device__ inline float xla_tanhf(float x){
    float cx = fminf(fmaxf(x, -7.90531110763549805f), 7.90531110763549805f);
    float x2 = __fmul_rn(cx, cx);
    float p = fmaf(x2, -2.76076847742355e-16f, 2.00018790482477e-13f);
    p = fmaf(x2, p, -8.60467152213735e-11f);
    p = fmaf(x2, p,  5.12229709037114e-08f);
    p = fmaf(x2, p,  1.48572235717979e-05f);
    p = fmaf(x2, p,  6.37261928875436e-04f);
    p = fmaf(x2, p,  4.89352455891786e-03f);
    p = __fmul_rn(cx, p);
    float q = fmaf(x2, 1.19825839466702e-06f, 1.18534705686654e-04f);
    q = fmaf(x2, q, 2.26843463243900e-03f);
    q = fmaf(x2, q, 4.89352518554385e-03f);
    float r = __fdiv_rn(p, q);
    return (fabsf(x) < 0.0004f) ? x : r;
}

/* logistic: XLA LogisticExpander — 0.5 + 0.5*tanh(0.5*x) */
__device__ inline float xla_logistic(float x){
    float t = xla_tanhf(__fmul_rn(0.5f, x));
    return __fadd_rn(0.5f, __fmul_rn(0.5f, t));
}

__device__ inline float wredsum(float v){
    #pragma unroll
    for (int o = 16; o; o >>= 1) v += __shfl_xor_sync(0xffffffffu, v, o);
    return v;
}

/* ---------------- JAX associative_scan (odd-even recursion), exact tree ---------------- */
template<int N>
__device__ inline void ascan_mul(const float* x, float* out){
    if constexpr (N == 1){
        out[0] = x[0];
    } else {
        constexpr int NR = N/2;
        float red[NR], odd[NR];
        #pragma unroll
        for (int i = 0; i < NR; i++) red[i] = __fmul_rn(x[2*i], x[2*i+1]);
        ascan_mul<NR>(red, odd);
        out[0] = x[0];
        #pragma unroll
        for (int i = 1; i < (N+1)/2; i++) out[2*i] = __fmul_rn(odd[i-1], x[2*i]);
        #pragma unroll
        for (int i = 0; i < NR; i++) out[2*i+1] = odd[i];
    }
}

template<int N>
__device__ inline void ascan_add(const float* x, float* out){
    if constexpr (N == 1){
        out[0] = x[0];
    } else {
        constexpr int NR = N/2;
        float red[NR], odd[NR];
        #pragma unroll
        for (int i = 0; i < NR; i++) red[i] = __fadd_rn(x[2*i], x[2*i+1]);
        ascan_add<NR>(red, odd);
        out[0] = x[0];
        #pragma unroll
        for (int i = 1; i < (N+1)/2; i++) out[2*i] = __fadd_rn(odd[i-1], x[2*i]);
        #pragma unroll
        for (int i = 0; i < NR; i++) out[2*i+1] = odd[i];
    }
}

/* ---------------- kernels ---------------- */
__global__ void k_init(){
    g_dminU = 0xFFFFFFFFu;
    g_dmaxU = 0u;
}

__global__ void k_transpose(const float* __restrict__ planes){
    __shared__ float sh[32][33];
    int bp   = blockIdx.y;
    int pos0 = blockIdx.x * 32;
    int tx = threadIdx.x, ty = threadIdx.y;
    sh[ty][tx] = planes[(size_t)(bp*32 + ty)*65536 + pos0 + tx];
    __syncthreads();
    g_tp[((size_t)bp*65536 + pos0 + ty)*32 + tx] = sh[tx][ty];
}

__global__ void k_gencoarse(const float* __restrict__ orig, unsigned kz0, unsigned kz1){
    int t = blockIdx.x * blockDim.x + threadIdx.x;
    if (t >= NPTS) return;
    int ray = t / 48, s = t - ray*48;
    float u = uniform01(kz0, kz1, (unsigned)t);
    const float step = 1.0f/47.0f;
    float lin = __fadd_rn(0.5f, __fmul_rn((float)s, step));
    /* CPU XLA: separate mul and add, no contraction */
    float d = __fadd_rn(__fadd_rn(lin, __fmul_rn(u, step)), -orig[ray*3+2]);
    g_dep[ray*96 + s] = d;
    unsigned b = __float_as_uint(d);
    unsigned m = (b & 0x80000000u) ? ~b : (b | 0x80000000u);
    atomicMin(&g_dminU, m);
    atomicMax(&g_dmaxU, m);
}

/* per-plane bilinear sample (value F with exact reference op-order) + grad accum */
__device__ inline void plane_acc(int bp, float gx, float gy, int lane,
                                 float &F, float &Dx, float &Dy){
    float px = __fadd_rn(__fmul_rn(__fadd_rn(gx, 1.0f), 128.0f), -0.5f);
    float py = __fadd_rn(__fmul_rn(__fadd_rn(gy, 1.0f), 128.0f), -0.5f);
    float x0f = floorf(px), y0f = floorf(py);
    float wx = __fadd_rn(px, -x0f), wy = __fadd_rn(py, -y0f);
    int x0 = (int)x0f, y0 = (int)y0f;
    float acc = 0.0f;
    #pragma unroll
    for (int j = 0; j < 2; j++){
        #pragma unroll
        for (int i = 0; i < 2; i++){
            int ix = x0 + i, iy = y0 + j;
            float m = (ix >= 0 && ix < 256 && iy >= 0 && iy < 256) ? 1.0f : 0.0f;
            int ic = min(max(ix, 0), 255), jc = min(max(iy, 0), 255);
            float v = g_tp[((size_t)(bp*256 + jc)*256 + ic)*32 + lane];
            float wxi = i ? wx : __fadd_rn(1.0f, -wx);
            float wyj = j ? wy : __fadd_rn(1.0f, -wy);
            float w = __fmul_rn(__fmul_rn(wxi, wyj), m);
            acc = __fadd_rn(acc, __fmul_rn(v, w));
            Dx = __fadd_rn(Dx, __fmul_rn(v, __fmul_rn(m, (i ? wyj : -wyj))));
            Dy = __fadd_rn(Dy, __fmul_rn(v, __fmul_rn(m, (j ? wxi : -wxi))));
        }
    }
    F = acc;
}

__global__ void __launch_bounds__(256)
k_model(const float* __restrict__ orig, const float* __restrict__ dirs,
        const float* __restrict__ w1, const float* __restrict__ b1,
        const float* __restrict__ w2, const float* __restrict__ b2,
        const float* __restrict__ betap, float* __restrict__ out, int fine)
{
    __shared__ float w1s[32*65];
    __shared__ float w2s[64*33];
    __shared__ float b1s[64], b2s[33];
    int tid = threadIdx.x;
    for (int i = tid; i < 2048; i += blockDim.x){ int c = i >> 6, k = i & 63; w1s[c*65 + k] = w1[i]; }
    for (int i = tid; i < 2112; i += blockDim.x) w2s[i] = w2[i];
    if (tid < 64) b1s[tid] = b1[tid];
    if (tid < 33) b2s[tid] = b2[tid];
    __syncthreads();

    int lane = tid & 31;
    int pt = blockIdx.x * (blockDim.x >> 5) + (tid >> 5);
    if (pt >= NPTS) return;
    int ray = pt / 48, s = pt - ray*48;
    int slot = ray*96 + s + (fine ? 48 : 0);
    float depth = g_dep[slot];
    float ox = orig[ray*3], oy = orig[ray*3+1], oz = orig[ray*3+2];
    float dx = dirs[ray*3], dy = dirs[ray*3+1], dz = dirs[ray*3+2];
    /* CPU XLA: separate mul and add, no contraction */
    float cx = __fadd_rn(ox, __fmul_rn(depth, dx));
    float cy = __fadd_rn(oy, __fmul_rn(depth, dy));
    float cz = __fadd_rn(oz, __fmul_rn(depth, dz));
    int b = ray >> 11;

    float F0, F1, F2, GX = 0.f, GY = 0.f, GZ = 0.f;
    plane_acc(b*3 + 0, cx, cy, lane, F0, GX, GY);   /* (x,y) */
    plane_acc(b*3 + 1, cx, cz, lane, F1, GX, GZ);   /* (x,z) */
    plane_acc(b*3 + 2, cz, cy, lane, F2, GZ, GY);   /* (z,y) */
    float Fd = __fdiv_rn(__fadd_rn(__fadd_rn(F0, F1), F2), 3.0f);

    /* layer 1: gemm semantics — fma chain from 0, ascending c, bias added after */
    float pa = 0.f, pb = 0.f;
    #pragma unroll
    for (int c = 0; c < 32; c++){
        float xc = __shfl_sync(0xffffffffu, Fd, c);
        pa = fmaf(xc, w1s[c*65 + lane],      pa);
        pb = fmaf(xc, w1s[c*65 + lane + 32], pb);
    }
    pa = __fadd_rn(pa, b1s[lane]);
    pb = __fadd_rn(pb, b1s[lane + 32]);
    /* softplus = max(x,0) + log1p(exp(-|x|)) with XLA CPU exp/log1p */
    float ha = __fadd_rn(fmaxf(pa, 0.f), xla_log1pf(xla_expf(-fabsf(pa))));
    float hb = __fadd_rn(fmaxf(pb, 0.f), xla_log1pf(xla_expf(-fabsf(pb))));
    /* softplus' via logaddexp custom-jvp: exp(x - softplus(x)) */
    float sa = xla_expf(__fadd_rn(pa, -ha));
    float sb = xla_expf(__fadd_rn(pb, -hb));

    /* layer 2: fma chain from 0 + bias after; plus backprop vector t */
    float o = 0.f, o2 = 0.f, tcc = 0.f;
    #pragma unroll
    for (int k = 0; k < 64; k++){
        float hk = __shfl_sync(0xffffffffu, (k < 32) ? ha : hb, k & 31);
        float sk = __shfl_sync(0xffffffffu, (k < 32) ? sa : sb, k & 31);
        float w20 = w2s[k*33];
        o   = fmaf(hk, w2s[k*33 + lane], o);
        o2  = fmaf(hk, w2s[k*33 + 32],  o2);
        tcc = fmaf(__fmul_rn(sk, w20), w1s[lane*65 + k], tcc);
    }
    o  = __fadd_rn(o,  b2s[lane]);
    o2 = __fadd_rn(o2, b2s[32]);

    float gxr = __fmul_rn(wredsum(__fmul_rn(tcc, GX)), (128.0f/3.0f));
    float gyr = __fmul_rn(wredsum(__fmul_rn(tcc, GY)), (128.0f/3.0f));
    float gzr = __fmul_rn(wredsum(__fmul_rn(tcc, GZ)), (128.0f/3.0f));
    float sigma = __shfl_sync(0xffffffffu, o, 0);

    if (lane >= 1) g_rgb[(size_t)slot*32 + (lane-1)] = __fadd_rn(__fmul_rn(xla_logistic(o), 1.002f), -0.001f);
    if (lane == 31) g_rgb[(size_t)slot*32 + 31] = __fadd_rn(__fmul_rn(xla_logistic(o2), 1.002f), -0.001f);

    if (lane == 0){
        float beta = betap[0];
        float r2 = __fadd_rn(__fadd_rn(__fadd_rn(__fmul_rn(cx,cx), __fmul_rn(cy,cy)), __fmul_rn(cz,cz)), 1e-12f);
        float rs = sqrtf(r2);
        float sdf = __fadd_rn(sigma, __fadd_rn(rs, -0.5f));
        float inv = __fdiv_rn(1.0f, rs);
        float gax = __fadd_rn(gxr, __fmul_rn(cx, inv));
        float gay = __fadd_rn(gyr, __fmul_rn(cy, inv));
        float gaz = __fadd_rn(gzr, __fmul_rn(cz, inv));
        int r = ray & 2047;
        int m = r*48 + s;
        int pidx = b*196608 + (fine ? 98304 : 0) + m;
        out[OFF_SDF + pidx] = sdf;
        out[OFF_GC + (size_t)pidx*3 + 0] = gax;
        out[OFF_GC + (size_t)pidx*3 + 1] = gay;
        out[OFF_GC + (size_t)pidx*3 + 2] = gaz;
        /* density = logistic(-sdf/beta)/beta */
        float y = __fdiv_rn(-sdf, beta);
        g_dens[slot] = __fdiv_rn(xla_logistic(y), beta);
        float nx = -gax;
        float nrm = fmaxf(sqrtf(__fadd_rn(__fadd_rn(__fmul_rn(nx,nx), __fmul_rn(gay,gay)), __fmul_rn(gaz,gaz))), 1e-12f);
        g_gn[(size_t)slot*3 + 0] = __fdiv_rn(nx, nrm);
        g_gn[(size_t)slot*3 + 1] = __fdiv_rn(gay, nrm);
        g_gn[(size_t)slot*3 + 2] = __fdiv_rn(gaz, nrm);
    }
}

__global__ void k_marchimp(unsigned ku0, unsigned ku1){
    int ray = blockIdx.x * blockDim.x + threadIdx.x;
    if (ray >= NRAY) return;
    int rb = ray*96;
    float z[48], dn[48];
    for (int i = 0; i < 48; i++){ z[i] = g_dep[rb+i]; dn[i] = g_dens[rb+i]; }
    /* alpha + shifted, then cumprod via JAX associative_scan tree */
    float alpha[47], shifted[48];
    shifted[0] = 1.0f;
    for (int i = 0; i < 47; i++){
        float dm = __fmul_rn(0.5f, __fadd_rn(dn[i], dn[i+1]));
        float dt = __fadd_rn(z[i+1], -z[i]);
        float a = __fadd_rn(1.0f, -xla_expf(-__fmul_rn(dm, dt)));
        alpha[i] = a;
        shifted[i+1] = __fadd_rn(__fadd_rn(1.0f, -a), 1e-10f);
    }
    float cp[48];
    ascan_mul<48>(shifted, cp);
    float w[47];
    for (int i = 0; i < 47; i++) w[i] = __fmul_rn(alpha[i], cp[i]);

    float p[45];
    for (int k = 0; k < 45; k++){
        int i = k + 1;
        float wm0 = fmaxf(w[i-1], w[i]);
        float wm1 = fmaxf(w[i], w[i+1]);
        /* CPU XLA: separate mul and add */
        float wa = __fadd_rn(__fmul_rn(0.5f, __fadd_rn(wm0, wm1)), 0.01f);
        p[k] = __fadd_rn(wa, 1e-5f);
    }
    /* CPU XLA reduce: sequential ascending from 0 */
    float sum = 0.0f;
    for (int k = 0; k < 45; k++) sum = __fadd_rn(sum, p[k]);

    /* normalized pdf, then cumsum via JAX associative_scan tree */
    float pn[45];
    for (int k = 0; k < 45; k++) pn[k] = __fdiv_rn(p[k], sum);
    float cs[45];
    ascan_add<45>(pn, cs);
    float cdf[46]; cdf[0] = 0.0f;
    for (int k = 0; k < 45; k++) cdf[k+1] = cs[k];

    float zm[47];
    for (int i = 0; i < 47; i++) zm[i] = __fmul_rn(0.5f, __fadd_rn(z[i], z[i+1]));
    for (int j = 0; j < 48; j++){
        float u = uniform01(ku0, ku1, (unsigned)(ray*48 + j));
        int lo = 0, hi = 46;
        while (lo < hi){ int mid = (lo + hi) >> 1; if (cdf[mid] <= u) lo = mid + 1; else hi = mid; }
        int below = lo - 1 > 0 ? lo - 1 : 0;
        int above = lo < 45 ? lo : 45;
        float c0 = cdf[below], c1 = cdf[above];
        float b0 = zm[below], b1 = zm[above];
        float diff = __fadd_rn(c1, -c0);
        float den = (diff < 1e-5f) ? 1.0f : diff;
        float fr = __fdiv_rn(__fadd_rn(u, -c0), den);
        /* CPU XLA: separate mul and add */
        g_dep[rb + 48 + j] = __fadd_rn(b0, __fmul_rn(fr, __fadd_rn(b1, -b0)));
    }
}

__global__ void k_merge(float* __restrict__ out){
    int ray = blockIdx.x * blockDim.x + threadIdx.x;
    if (ray >= NRAY) return;
    int rb = ray*96;
    float zc[48], zf[48]; int fi[48];
    for (int i = 0; i < 48; i++) zc[i] = g_dep[rb + i];
    for (int j = 0; j < 48; j++){ zf[j] = g_dep[rb + 48 + j]; fi[j] = j; }
    for (int j = 1; j < 48; j++){
        float v = zf[j]; int id = fi[j]; int k = j - 1;
        while (k >= 0 && zf[k] > v){ zf[k+1] = zf[k]; fi[k+1] = fi[k]; k--; }
        zf[k+1] = v; fi[k+1] = id;
    }
    float Dm[96]; int od[96];
    {
        int i = 0, j = 0;
        for (int n = 0; n < 96; n++){
            bool tc = (j >= 48) || (i < 48 && zc[i] <= zf[j]);
            if (tc){ Dm[n] = zc[i]; od[n] = i; i++; }
            else   { Dm[n] = zf[j]; od[n] = 48 + fi[j]; j++; }
            g_ord[rb + n] = od[n];
        }
    }
    /* final march: alphas with XLA exp, weights via ascan cumprod to match */
    float alpha[95], shifted[96];
    shifted[0] = 1.0f;
    {
        float dprev = g_dens[rb + od[0]];
        for (int n = 0; n < 95; n++){
            float dnx = g_dens[rb + od[n+1]];
            float dt = __fadd_rn(Dm[n+1], -Dm[n]);
            float dm = __fmul_rn(0.5f, __fadd_rn(dprev, dnx));
            float a = __fadd_rn(1.0f, -xla_expf(-__fmul_rn(dm, dt)));
            alpha[n] = a;
            shifted[n+1] = __fadd_rn(__fadd_rn(1.0f, -a), 1e-10f);
            dprev = dnx;
        }
    }
    float cp[96];
    ascan_mul<96>(shifted, cp);

    float wtot = 0.0f, dsum = 0.0f, s0 = 0.f, s1 = 0.f, s2 = 0.f;
    float gp0 = g_gn[(size_t)(rb+od[0])*3],   gp1 = g_gn[(size_t)(rb+od[0])*3+1],
          gp2 = g_gn[(size_t)(rb+od[0])*3+2];
    for (int n = 0; n < 95; n++){
        int o1 = od[n+1];
        float gq0 = g_gn[(size_t)(rb+o1)*3], gq1 = g_gn[(size_t)(rb+o1)*3+1], gq2 = g_gn[(size_t)(rb+o1)*3+2];
        float wgt = __fmul_rn(alpha[n], cp[n]);
        g_w[(size_t)ray*95 + n] = wgt;
        wtot = __fadd_rn(wtot, wgt);
        dsum = __fadd_rn(dsum, __fmul_rn(wgt, __fmul_rn(0.5f, __fadd_rn(Dm[n], Dm[n+1]))));
        s0 = __fadd_rn(s0, __fmul_rn(wgt, __fmul_rn(0.5f, __fadd_rn(gp0, gq0))));
        s1 = __fadd_rn(s1, __fmul_rn(wgt, __fmul_rn(0.5f, __fadd_rn(gp1, gq1))));
        s2 = __fadd_rn(s2, __fmul_rn(wgt, __fmul_rn(0.5f, __fadd_rn(gp2, gq2))));
        gp0 = gq0; gp1 = gq1; gp2 = gq2;
    }
    float depth = __fdiv_rn(dsum, fmaxf(wtot, 1e-12f));
    unsigned mu = g_dminU; unsigned bu = (mu >> 31) ? (mu ^ 0x80000000u) : ~mu;
    unsigned mx = g_dmaxU; unsigned bx = (mx >> 31) ? (mx ^ 0x80000000u) : ~mx;
    float dmin = __uint_as_float(bu), dmax = __uint_as_float(bx);
    depth = fminf(fmaxf(depth, dmin), dmax);
    out[OFF_DEPTH + ray] = depth;
    out[OFF_WSUM + ray] = wtot;
    out[OFF_GRAD + (size_t)ray*3 + 0] = s0;
    out[OFF_GRAD + (size_t)ray*3 + 1] = s1;
    out[OFF_GRAD + (size_t)ray*3 + 2] = s2;
}

__global__ void k_rgbacc(float* __restrict__ out){
    int lane = threadIdx.x & 31;
    int ray = blockIdx.x * (blockDim.x >> 5) + (threadIdx.x >> 5);
    if (ray >= NRAY) return;
    int rb = ray*96;
    int o0 = g_ord[rb];
    float prev = g_rgb[(size_t)(rb + o0)*32 + lane];
    float acc = 0.0f;
    for (int i = 0; i < 95; i++){
        int oi = g_ord[rb + i + 1];
        float cur = g_rgb[(size_t)(rb + oi)*32 + lane];
        float wgt = g_w[(size_t)ray*95 + i];
        acc = __fadd_rn(acc, __fmul_rn(wgt, __fmul_rn(0.5f, __fadd_rn(prev, cur))));
        prev = cur;
    }
    out[OFF_RGB + (size_t)ray*32 + lane] = __fadd_rn(__fmul_rn(acc, 2.0f), -1.0f);
}

/* ---------------- launch ---------------- */
extern "C" void kernel_launch(void* const* d_in, const int* in_sizes, int n_in,
                              void* d_out, int out_size){
    const float* planes = (const float*)d_in[0];
    const float* orig   = (const float*)d_in[1];
    const float* dirs   = (const float*)d_in[2];
    const float* w1     = (const float*)d_in[3];
    const float* b1     = (const float*)d_in[4];
    const float* w2     = (const float*)d_in[5];
    const float* b2     = (const float*)d_in[6];
    const float* beta   = (const float*)d_in[7];
    float* out = (float*)d_out;

    unsigned kz0, kz1, ku0, ku1;
    tf2x32(0u, 42u, 0u, 0u, kz0, kz1);
    tf2x32(0u, 42u, 0u, 1u, ku0, ku1);

    k_init<<<1, 1>>>();
    k_transpose<<<dim3(2048, 6), dim3(32, 32)>>>(planes);
    k_gencoarse<<<768, 256>>>(orig, kz0, kz1);
    k_model<<<24576, 256>>>(orig, dirs, w1, b1, w2, b2, beta, out, 0);
    k_marchimp<<<16, 256>>>(ku0, ku1);
    k_model<<<24576, 256>>>(orig, dirs, w1, b1, w2, b2, beta, out, 1);
    k_merge<<<16, 256>>>(out);
    k_rgbacc<<<512, 256>>>(out);
}

// round 12
// speedup vs baseline: 1.3374x; 1.3374x over previous
#include <cuda_runtime.h>
#include <cstdint>
#include <math.h>

#define NRAY 4096
#define NPTS 196608   /* NRAY * 48 */

/* output offsets (floats) */
#define OFF_RGB   0
#define OFF_DEPTH 131072
#define OFF_WSUM  135168
#define OFF_GRAD  139264
#define OFF_GC    151552
#define OFF_SDF   1331200

/* scratch */
__device__ float    g_tp  [2*3*256*256*32]; /* [b][p][y][x][c] */
__device__ float    g_dep [NRAY*96];
__device__ float    g_dens[NRAY*96];
__device__ float    g_rgb [NRAY*96*32];
__device__ float    g_gn  [NRAY*96*3];
__device__ float    g_w   [NRAY*95];
__device__ int      g_ord [NRAY*96];
__device__ unsigned g_dminU, g_dmaxU;

/* ---------------- Threefry2x32-20 (JAX partitionable) ---------------- */
__host__ __device__ inline unsigned rotl32(unsigned v, int r){ return (v<<r)|(v>>(32-r)); }

__host__ __device__ inline void tf2x32(unsigned k0, unsigned k1, unsigned x0, unsigned x1,
                                       unsigned &o0, unsigned &o1){
    unsigned k2 = k0 ^ k1 ^ 0x1BD11BDAu;
    x0 += k0; x1 += k1;
#define TF_R(r) { x0 += x1; x1 = rotl32(x1,(r)); x1 ^= x0; }
    TF_R(13) TF_R(15) TF_R(26) TF_R(6)
    x0 += k1; x1 += k2 + 1u;
    TF_R(17) TF_R(29) TF_R(16) TF_R(24)
    x0 += k2; x1 += k0 + 2u;
    TF_R(13) TF_R(15) TF_R(26) TF_R(6)
    x0 += k0; x1 += k1 + 3u;
    TF_R(17) TF_R(29) TF_R(16) TF_R(24)
    x0 += k1; x1 += k2 + 4u;
    TF_R(13) TF_R(15) TF_R(26) TF_R(6)
    x0 += k2; x1 += k0 + 5u;
#undef TF_R
    o0 = x0; o1 = x1;
}

__device__ inline float uniform01(unsigned k0, unsigned k1, unsigned idx){
    unsigned a, b;
    tf2x32(k0, k1, 0u, idx, a, b);
    unsigned bits = a ^ b;
    unsigned fb = (bits >> 9) | 0x3F800000u;
    float f = __fadd_rn(__uint_as_float(fb), -1.0f);
    return fmaxf(0.0f, f);
}

/* ---------------- XLA:CPU math replicas (llvm_ir_runtime / Cephes) ---------------- */
__device__ inline float xla_expf(float x){
    float cx = fminf(fmaxf(x, -88.3762626647949f), 88.3762626647950f);
    float fx = floorf(fmaf(cx, 1.44269504088896341f, 0.5f));
    float r = fmaf(-0.693359375f, fx, cx);
    r = fmaf(2.12194440e-4f, fx, r);
    float z = __fmul_rn(r, r);
    float y = 1.9875691500e-4f;
    y = fmaf(y, r, 1.3981999507e-3f);
    y = fmaf(y, r, 8.3334519073e-3f);
    y = fmaf(y, r, 4.1665795894e-2f);
    y = fmaf(y, r, 1.6666665459e-1f);
    y = fmaf(y, r, 5.0000001201e-1f);
    y = fmaf(y, z, r);
    y = __fadd_rn(1.0f, y);
    int n = (int)fx;
    float s = __uint_as_float((unsigned)((n + 127) << 23));
    return __fmul_rn(y, s);
}

__device__ inline float xla_logf(float u){
    unsigned iu = __float_as_uint(u);
    int e = (int)(iu >> 23) - 126;
    float m = __uint_as_float((iu & 0x007FFFFFu) | 0x3F000000u);
    float x;
    if (m < 0.707106781186547524f){ e -= 1; x = __fadd_rn(__fadd_rn(m, -1.0f), m); }
    else                          { x = __fadd_rn(m, -1.0f); }
    float z = __fmul_rn(x, x);
    float y = 7.0376836292e-2f;
    y = fmaf(y, x, -1.1514610310e-1f);
    y = fmaf(y, x,  1.1676998740e-1f);
    y = fmaf(y, x, -1.2420140846e-1f);
    y = fmaf(y, x,  1.4249322787e-1f);
    y = fmaf(y, x, -1.6668057665e-1f);
    y = fmaf(y, x,  2.0000714765e-1f);
    y = fmaf(y, x, -2.4999993993e-1f);
    y = fmaf(y, x,  3.3333331174e-1f);
    y = __fmul_rn(__fmul_rn(y, x), z);
    float ef = (float)e;
    y = fmaf(ef, -2.12194440e-4f, y);
    y = fmaf(z, -0.5f, y);
    x = __fadd_rn(x, y);
    x = fmaf(ef, 0.693359375f, x);
    return x;
}

__device__ inline float xla_log1pf(float x){
    float large_ = xla_logf(__fadd_rn(x, 1.0f));
    float small_ = __fmul_rn(fmaf(-0.5f, x, 1.0f), x);
    return (fabsf(x) < 1e-4f) ? small_ : large_;
}

__device__ inline float xla_tanhf(float x){
    float cx = fminf(fmaxf(x, -7.90531110763549805f), 7.90531110763549805f);
    float x2 = __fmul_rn(cx, cx);
    float p = fmaf(x2, -2.76076847742355e-16f, 2.00018790482477e-13f);
    p = fmaf(x2, p, -8.60467152213735e-11f);
    p = fmaf(x2, p,  5.12229709037114e-08f);
    p = fmaf(x2, p,  1.48572235717979e-05f);
    p = fmaf(x2, p,  6.37261928875436e-04f);
    p = fmaf(x2, p,  4.89352455891786e-03f);
    p = __fmul_rn(cx, p);
    float q = fmaf(x2, 1.19825839466702e-06f, 1.18534705686654e-04f);
    q = fmaf(x2, q, 2.26843463243900e-03f);
    q = fmaf(x2, q, 4.89352518554385e-03f);
    float r = __fdiv_rn(p, q);
    return (fabsf(x) < 0.0004f) ? x : r;
}

__device__ inline float xla_logistic(float x){
    float t = xla_tanhf(__fmul_rn(0.5f, x));
    return __fadd_rn(0.5f, __fmul_rn(0.5f, t));
}

__device__ inline float wredsum(float v){
    #pragma unroll
    for (int o = 16; o; o >>= 1) v += __shfl_xor_sync(0xffffffffu, v, o);
    return v;
}

/* ---------------- JAX associative_scan (odd-even recursion), exact tree ---------------- */
template<int N>
__device__ inline void ascan_mul(const float* x, float* out){
    if constexpr (N == 1){
        out[0] = x[0];
    } else {
        constexpr int NR = N/2;
        float red[NR], odd[NR];
        #pragma unroll
        for (int i = 0; i < NR; i++) red[i] = __fmul_rn(x[2*i], x[2*i+1]);
        ascan_mul<NR>(red, odd);
        out[0] = x[0];
        #pragma unroll
        for (int i = 1; i < (N+1)/2; i++) out[2*i] = __fmul_rn(odd[i-1], x[2*i]);
        #pragma unroll
        for (int i = 0; i < NR; i++) out[2*i+1] = odd[i];
    }
}

template<int N>
__device__ inline void ascan_add(const float* x, float* out){
    if constexpr (N == 1){
        out[0] = x[0];
    } else {
        constexpr int NR = N/2;
        float red[NR], odd[NR];
        #pragma unroll
        for (int i = 0; i < NR; i++) red[i] = __fadd_rn(x[2*i], x[2*i+1]);
        ascan_add<NR>(red, odd);
        out[0] = x[0];
        #pragma unroll
        for (int i = 1; i < (N+1)/2; i++) out[2*i] = __fadd_rn(odd[i-1], x[2*i]);
        #pragma unroll
        for (int i = 0; i < NR; i++) out[2*i+1] = odd[i];
    }
}

/* ---------------- kernels ---------------- */
__global__ void k_init(){
    g_dminU = 0xFFFFFFFFu;
    g_dmaxU = 0u;
}

__global__ void k_transpose(const float* __restrict__ planes){
    __shared__ float sh[32][33];
    int bp   = blockIdx.y;
    int pos0 = blockIdx.x * 32;
    int tx = threadIdx.x, ty = threadIdx.y;
    sh[ty][tx] = planes[(size_t)(bp*32 + ty)*65536 + pos0 + tx];
    __syncthreads();
    g_tp[((size_t)bp*65536 + pos0 + ty)*32 + tx] = sh[tx][ty];
}

__global__ void k_gencoarse(const float* __restrict__ orig, unsigned kz0, unsigned kz1){
    int t = blockIdx.x * blockDim.x + threadIdx.x;
    if (t >= NPTS) return;
    int ray = t / 48, s = t - ray*48;
    float u = uniform01(kz0, kz1, (unsigned)t);
    const float step = 1.0f/47.0f;
    float lin = __fadd_rn(0.5f, __fmul_rn((float)s, step));
    float d = __fadd_rn(__fadd_rn(lin, __fmul_rn(u, step)), -orig[ray*3+2]);
    g_dep[ray*96 + s] = d;
    unsigned b = __float_as_uint(d);
    unsigned m = (b & 0x80000000u) ? ~b : (b | 0x80000000u);
    atomicMin(&g_dminU, m);
    atomicMax(&g_dmaxU, m);
}

/* per-plane bilinear sample (value F with exact reference op-order) + grad accum */
__device__ inline void plane_acc(int bp, float gx, float gy, int lane,
                                 float &F, float &Dx, float &Dy){
    float px = __fadd_rn(__fmul_rn(__fadd_rn(gx, 1.0f), 128.0f), -0.5f);
    float py = __fadd_rn(__fmul_rn(__fadd_rn(gy, 1.0f), 128.0f), -0.5f);
    float x0f = floorf(px), y0f = floorf(py);
    float wx = __fadd_rn(px, -x0f), wy = __fadd_rn(py, -y0f);
    int x0 = (int)x0f, y0 = (int)y0f;
    float acc = 0.0f;
    #pragma unroll
    for (int j = 0; j < 2; j++){
        #pragma unroll
        for (int i = 0; i < 2; i++){
            int ix = x0 + i, iy = y0 + j;
            float m = (ix >= 0 && ix < 256 && iy >= 0 && iy < 256) ? 1.0f : 0.0f;
            int ic = min(max(ix, 0), 255), jc = min(max(iy, 0), 255);
            float v = g_tp[((size_t)(bp*256 + jc)*256 + ic)*32 + lane];
            float wxi = i ? wx : __fadd_rn(1.0f, -wx);
            float wyj = j ? wy : __fadd_rn(1.0f, -wy);
            float w = __fmul_rn(__fmul_rn(wxi, wyj), m);
            acc = __fadd_rn(acc, __fmul_rn(v, w));
            Dx = __fadd_rn(Dx, __fmul_rn(v, __fmul_rn(m, (i ? wyj : -wyj))));
            Dy = __fadd_rn(Dy, __fmul_rn(v, __fmul_rn(m, (j ? wxi : -wxi))));
        }
    }
    F = acc;
}

__global__ void __launch_bounds__(256)
k_model(const float* __restrict__ orig, const float* __restrict__ dirs,
        const float* __restrict__ w1, const float* __restrict__ b1,
        const float* __restrict__ w2, const float* __restrict__ b2,
        const float* __restrict__ betap, float* __restrict__ out, int fine)
{
    __shared__ float w1s[32*65];
    __shared__ float w2s[64*33];
    __shared__ float b1s[64], b2s[33];
    int tid = threadIdx.x;
    for (int i = tid; i < 2048; i += blockDim.x){ int c = i >> 6, k = i & 63; w1s[c*65 + k] = w1[i]; }
    for (int i = tid; i < 2112; i += blockDim.x) w2s[i] = w2[i];
    if (tid < 64) b1s[tid] = b1[tid];
    if (tid < 33) b2s[tid] = b2[tid];
    __syncthreads();

    int lane = tid & 31;
    int pt = blockIdx.x * (blockDim.x >> 5) + (tid >> 5);
    if (pt >= NPTS) return;
    int ray = pt / 48, s = pt - ray*48;
    int slot = ray*96 + s + (fine ? 48 : 0);
    float depth = g_dep[slot];
    float ox = orig[ray*3], oy = orig[ray*3+1], oz = orig[ray*3+2];
    float dx = dirs[ray*3], dy = dirs[ray*3+1], dz = dirs[ray*3+2];
    float cx = __fadd_rn(ox, __fmul_rn(depth, dx));
    float cy = __fadd_rn(oy, __fmul_rn(depth, dy));
    float cz = __fadd_rn(oz, __fmul_rn(depth, dz));
    int b = ray >> 11;

    /* register-resident w2 columns 0 and 32 for this lane's k = lane, lane+32 */
    float w20a  = w2s[lane*33];
    float w20b  = w2s[(lane+32)*33];
    float w232a = w2s[lane*33 + 32];
    float w232b = w2s[(lane+32)*33 + 32];

    float F0, F1, F2, GX = 0.f, GY = 0.f, GZ = 0.f;
    plane_acc(b*3 + 0, cx, cy, lane, F0, GX, GY);   /* (x,y) */
    plane_acc(b*3 + 1, cx, cz, lane, F1, GX, GZ);   /* (x,z) */
    plane_acc(b*3 + 2, cz, cy, lane, F2, GZ, GY);   /* (z,y) */
    float Fd = __fdiv_rn(__fadd_rn(__fadd_rn(F0, F1), F2), 3.0f);

    /* layer 1: gemm semantics — fma chain from 0, ascending c, bias added after */
    float pa = 0.f, pb = 0.f;
    #pragma unroll
    for (int c = 0; c < 32; c++){
        float xc = __shfl_sync(0xffffffffu, Fd, c);
        pa = fmaf(xc, w1s[c*65 + lane],      pa);
        pb = fmaf(xc, w1s[c*65 + lane + 32], pb);
    }
    pa = __fadd_rn(pa, b1s[lane]);
    pb = __fadd_rn(pb, b1s[lane + 32]);
    /* softplus = max(x,0) + log1p(exp(-|x|)) with XLA CPU exp/log1p */
    float ha = __fadd_rn(fmaxf(pa, 0.f), xla_log1pf(xla_expf(-fabsf(pa))));
    float hb = __fadd_rn(fmaxf(pb, 0.f), xla_log1pf(xla_expf(-fabsf(pb))));
    /* softplus' via logaddexp custom-jvp: exp(x - softplus(x)) */
    float sa = xla_expf(__fadd_rn(pa, -ha));
    float sb = xla_expf(__fadd_rn(pb, -hb));

    /* tcc coefficients: q[k] = s[k]*w2[k][0], computed in-lane (bit-identical product) */
    float qa = __fmul_rn(sa, w20a);
    float qb = __fmul_rn(sb, w20b);

    /* layer 2: o chain exact (sigma-critical); tcc chain exact via shuffled q */
    float o = 0.f, tcc = 0.f;
    #pragma unroll
    for (int k = 0; k < 64; k++){
        float hk = __shfl_sync(0xffffffffu, (k < 32) ? ha : hb, k & 31);
        float qk = __shfl_sync(0xffffffffu, (k < 32) ? qa : qb, k & 31);
        o   = fmaf(hk, w2s[k*33 + lane], o);
        tcc = fmaf(qk, w1s[lane*65 + k], tcc);
    }
    o = __fadd_rn(o, b2s[lane]);
    /* o2 (rgb[31] only — smooth output, tree-sum reorder is ulp-harmless) */
    float o2 = wredsum(__fadd_rn(__fmul_rn(ha, w232a), __fmul_rn(hb, w232b)));
    o2 = __fadd_rn(o2, b2s[32]);

    float gxr = __fmul_rn(wredsum(__fmul_rn(tcc, GX)), (128.0f/3.0f));
    float gyr = __fmul_rn(wredsum(__fmul_rn(tcc, GY)), (128.0f/3.0f));
    float gzr = __fmul_rn(wredsum(__fmul_rn(tcc, GZ)), (128.0f/3.0f));
    float sigma = __shfl_sync(0xffffffffu, o, 0);

    if (lane >= 1) g_rgb[(size_t)slot*32 + (lane-1)] = __fadd_rn(__fmul_rn(xla_logistic(o), 1.002f), -0.001f);
    if (lane == 31) g_rgb[(size_t)slot*32 + 31] = __fadd_rn(__fmul_rn(xla_logistic(o2), 1.002f), -0.001f);

    if (lane == 0){
        float beta = betap[0];
        float r2 = __fadd_rn(__fadd_rn(__fadd_rn(__fmul_rn(cx,cx), __fmul_rn(cy,cy)), __fmul_rn(cz,cz)), 1e-12f);
        float rs = sqrtf(r2);
        float sdf = __fadd_rn(sigma, __fadd_rn(rs, -0.5f));
        float inv = __fdiv_rn(1.0f, rs);
        float gax = __fadd_rn(gxr, __fmul_rn(cx, inv));
        float gay = __fadd_rn(gyr, __fmul_rn(cy, inv));
        float gaz = __fadd_rn(gzr, __fmul_rn(cz, inv));
        int r = ray & 2047;
        int m = r*48 + s;
        int pidx = b*196608 + (fine ? 98304 : 0) + m;
        out[OFF_SDF + pidx] = sdf;
        out[OFF_GC + (size_t)pidx*3 + 0] = gax;
        out[OFF_GC + (size_t)pidx*3 + 1] = gay;
        out[OFF_GC + (size_t)pidx*3 + 2] = gaz;
        float y = __fdiv_rn(-sdf, beta);
        g_dens[slot] = __fdiv_rn(xla_logistic(y), beta);
        float nx = -gax;
        float nrm = fmaxf(sqrtf(__fadd_rn(__fadd_rn(__fmul_rn(nx,nx), __fmul_rn(gay,gay)), __fmul_rn(gaz,gaz))), 1e-12f);
        g_gn[(size_t)slot*3 + 0] = __fdiv_rn(nx, nrm);
        g_gn[(size_t)slot*3 + 1] = __fdiv_rn(gay, nrm);
        g_gn[(size_t)slot*3 + 2] = __fdiv_rn(gaz, nrm);
    }
}

__global__ void k_marchimp(unsigned ku0, unsigned ku1){
    int ray = blockIdx.x * blockDim.x + threadIdx.x;
    if (ray >= NRAY) return;
    int rb = ray*96;
    float z[48], dn[48];
    for (int i = 0; i < 48; i++){ z[i] = g_dep[rb+i]; dn[i] = g_dens[rb+i]; }
    float alpha[47], shifted[48];
    shifted[0] = 1.0f;
    for (int i = 0; i < 47; i++){
        float dm = __fmul_rn(0.5f, __fadd_rn(dn[i], dn[i+1]));
        float dt = __fadd_rn(z[i+1], -z[i]);
        float a = __fadd_rn(1.0f, -xla_expf(-__fmul_rn(dm, dt)));
        alpha[i] = a;
        shifted[i+1] = __fadd_rn(__fadd_rn(1.0f, -a), 1e-10f);
    }
    float cp[48];
    ascan_mul<48>(shifted, cp);
    float w[47];
    for (int i = 0; i < 47; i++) w[i] = __fmul_rn(alpha[i], cp[i]);

    float p[45];
    for (int k = 0; k < 45; k++){
        int i = k + 1;
        float wm0 = fmaxf(w[i-1], w[i]);
        float wm1 = fmaxf(w[i], w[i+1]);
        float wa = __fadd_rn(__fmul_rn(0.5f, __fadd_rn(wm0, wm1)), 0.01f);
        p[k] = __fadd_rn(wa, 1e-5f);
    }
    /* CPU XLA reduce: sequential ascending from 0 */
    float sum = 0.0f;
    for (int k = 0; k < 45; k++) sum = __fadd_rn(sum, p[k]);

    float pn[45];
    for (int k = 0; k < 45; k++) pn[k] = __fdiv_rn(p[k], sum);
    float cs[45];
    ascan_add<45>(pn, cs);
    float cdf[46]; cdf[0] = 0.0f;
    for (int k = 0; k < 45; k++) cdf[k+1] = cs[k];

    float zm[47];
    for (int i = 0; i < 47; i++) zm[i] = __fmul_rn(0.5f, __fadd_rn(z[i], z[i+1]));
    for (int j = 0; j < 48; j++){
        float u = uniform01(ku0, ku1, (unsigned)(ray*48 + j));
        int lo = 0, hi = 46;
        while (lo < hi){ int mid = (lo + hi) >> 1; if (cdf[mid] <= u) lo = mid + 1; else hi = mid; }
        int below = lo - 1 > 0 ? lo - 1 : 0;
        int above = lo < 45 ? lo : 45;
        float c0 = cdf[below], c1 = cdf[above];
        float b0 = zm[below], b1 = zm[above];
        float diff = __fadd_rn(c1, -c0);
        float den = (diff < 1e-5f) ? 1.0f : diff;
        float fr = __fdiv_rn(__fadd_rn(u, -c0), den);
        g_dep[rb + 48 + j] = __fadd_rn(b0, __fmul_rn(fr, __fadd_rn(b1, -b0)));
    }
}

__global__ void k_merge(float* __restrict__ out){
    int ray = blockIdx.x * blockDim.x + threadIdx.x;
    if (ray >= NRAY) return;
    int rb = ray*96;
    float zc[48], zf[48]; int fi[48];
    for (int i = 0; i < 48; i++) zc[i] = g_dep[rb + i];
    for (int j = 0; j < 48; j++){ zf[j] = g_dep[rb + 48 + j]; fi[j] = j; }
    for (int j = 1; j < 48; j++){
        float v = zf[j]; int id = fi[j]; int k = j - 1;
        while (k >= 0 && zf[k] > v){ zf[k+1] = zf[k]; fi[k+1] = fi[k]; k--; }
        zf[k+1] = v; fi[k+1] = id;
    }
    float Dm[96]; int od[96];
    {
        int i = 0, j = 0;
        for (int n = 0; n < 96; n++){
            bool tc = (j >= 48) || (i < 48 && zc[i] <= zf[j]);
            if (tc){ Dm[n] = zc[i]; od[n] = i; i++; }
            else   { Dm[n] = zf[j]; od[n] = 48 + fi[j]; j++; }
            g_ord[rb + n] = od[n];
        }
    }
    float alpha[95], shifted[96];
    shifted[0] = 1.0f;
    {
        float dprev = g_dens[rb + od[0]];
        for (int n = 0; n < 95; n++){
            float dnx = g_dens[rb + od[n+1]];
            float dt = __fadd_rn(Dm[n+1], -Dm[n]);
            float dm = __fmul_rn(0.5f, __fadd_rn(dprev, dnx));
            float a = __fadd_rn(1.0f, -xla_expf(-__fmul_rn(dm, dt)));
            alpha[n] = a;
            shifted[n+1] = __fadd_rn(__fadd_rn(1.0f, -a), 1e-10f);
            dprev = dnx;
        }
    }
    float cp[96];
    ascan_mul<96>(shifted, cp);

    float wtot = 0.0f, dsum = 0.0f, s0 = 0.f, s1 = 0.f, s2 = 0.f;
    float gp0 = g_gn[(size_t)(rb+od[0])*3],   gp1 = g_gn[(size_t)(rb+od[0])*3+1],
          gp2 = g_gn[(size_t)(rb+od[0])*3+2];
    for (int n = 0; n < 95; n++){
        int o1 = od[n+1];
        float gq0 = g_gn[(size_t)(rb+o1)*3], gq1 = g_gn[(size_t)(rb+o1)*3+1], gq2 = g_gn[(size_t)(rb+o1)*3+2];
        float wgt = __fmul_rn(alpha[n], cp[n]);
        g_w[(size_t)ray*95 + n] = wgt;
        wtot = __fadd_rn(wtot, wgt);
        dsum = __fadd_rn(dsum, __fmul_rn(wgt, __fmul_rn(0.5f, __fadd_rn(Dm[n], Dm[n+1]))));
        s0 = __fadd_rn(s0, __fmul_rn(wgt, __fmul_rn(0.5f, __fadd_rn(gp0, gq0))));
        s1 = __fadd_rn(s1, __fmul_rn(wgt, __fmul_rn(0.5f, __fadd_rn(gp1, gq1))));
        s2 = __fadd_rn(s2, __fmul_rn(wgt, __fmul_rn(0.5f, __fadd_rn(gp2, gq2))));
        gp0 = gq0; gp1 = gq1; gp2 = gq2;
    }
    float depth = __fdiv_rn(dsum, fmaxf(wtot, 1e-12f));
    unsigned mu = g_dminU; unsigned bu = (mu >> 31) ? (mu ^ 0x80000000u) : ~mu;
    unsigned mx = g_dmaxU; unsigned bx = (mx >> 31) ? (mx ^ 0x80000000u) : ~mx;
    float dmin = __uint_as_float(bu), dmax = __uint_as_float(bx);
    depth = fminf(fmaxf(depth, dmin), dmax);
    out[OFF_DEPTH + ray] = depth;
    out[OFF_WSUM + ray] = wtot;
    out[OFF_GRAD + (size_t)ray*3 + 0] = s0;
    out[OFF_GRAD + (size_t)ray*3 + 1] = s1;
    out[OFF_GRAD + (size_t)ray*3 + 2] = s2;
}

__global__ void k_rgbacc(float* __restrict__ out){
    int lane = threadIdx.x & 31;
    int ray = blockIdx.x * (blockDim.x >> 5) + (threadIdx.x >> 5);
    if (ray >= NRAY) return;
    int rb = ray*96;
    int o0 = g_ord[rb];
    float prev = g_rgb[(size_t)(rb + o0)*32 + lane];
    float acc = 0.0f;
    for (int i = 0; i < 95; i++){
        int oi = g_ord[rb + i + 1];
        float cur = g_rgb[(size_t)(rb + oi)*32 + lane];
        float wgt = g_w[(size_t)ray*95 + i];
        acc = __fadd_rn(acc, __fmul_rn(wgt, __fmul_rn(0.5f, __fadd_rn(prev, cur))));
        prev = cur;
    }
    out[OFF_RGB + (size_t)ray*32 + lane] = __fadd_rn(__fmul_rn(acc, 2.0f), -1.0f);
}

/* ---------------- launch ---------------- */
extern "C" void kernel_launch(void* const* d_in, const int* in_sizes, int n_in,
                              void* d_out, int out_size){
    const float* planes = (const float*)d_in[0];
    const float* orig   = (const float*)d_in[1];
    const float* dirs   = (const float*)d_in[2];
    const float* w1     = (const float*)d_in[3];
    const float* b1     = (const float*)d_in[4];
    const float* w2     = (const float*)d_in[5];
    const float* b2     = (const float*)d_in[6];
    const float* beta   = (const float*)d_in[7];
    float* out = (float*)d_out;

    unsigned kz0, kz1, ku0, ku1;
    tf2x32(0u, 42u, 0u, 0u, kz0, kz1);
    tf2x32(0u, 42u, 0u, 1u, ku0, ku1);

    k_init<<<1, 1>>>();
    k_transpose<<<dim3(2048, 6), dim3(32, 32)>>>(planes);
    k_gencoarse<<<768, 256>>>(orig, kz0, kz1);
    k_model<<<24576, 256>>>(orig, dirs, w1, b1, w2, b2, beta, out, 0);
    k_marchimp<<<128, 32>>>(ku0, ku1);
    k_model<<<24576, 256>>>(orig, dirs, w1, b1, w2, b2, beta, out, 1);
    k_merge<<<128, 32>>>(out);
    k_rgbacc<<<512, 256>>>(out);
}

// round 13
// speedup vs baseline: 1.6369x; 1.2240x over previous
#include <cuda_runtime.h>
#include <cstdint>
#include <math.h>

#define NRAY 4096
#define NPTS 196608   /* NRAY * 48 */

/* output offsets (floats) */
#define OFF_RGB   0
#define OFF_DEPTH 131072
#define OFF_WSUM  135168
#define OFF_GRAD  139264
#define OFF_GC    151552
#define OFF_SDF   1331200

/* scratch */
__device__ float    g_tp  [2*3*256*256*32]; /* [b][p][y][x][c] */
__device__ float    g_dep [NRAY*96];
__device__ float    g_dens[NRAY*96];
__device__ float    g_rgb [NRAY*96*32];
__device__ float    g_gn  [NRAY*96*3];
__device__ float    g_w   [NRAY*95];
__device__ int      g_ord [NRAY*96];
__device__ unsigned g_dminU, g_dmaxU;

/* ---------------- Threefry2x32-20 (JAX partitionable) ---------------- */
__host__ __device__ inline unsigned rotl32(unsigned v, int r){ return (v<<r)|(v>>(32-r)); }

__host__ __device__ inline void tf2x32(unsigned k0, unsigned k1, unsigned x0, unsigned x1,
                                       unsigned &o0, unsigned &o1){
    unsigned k2 = k0 ^ k1 ^ 0x1BD11BDAu;
    x0 += k0; x1 += k1;
#define TF_R(r) { x0 += x1; x1 = rotl32(x1,(r)); x1 ^= x0; }
    TF_R(13) TF_R(15) TF_R(26) TF_R(6)
    x0 += k1; x1 += k2 + 1u;
    TF_R(17) TF_R(29) TF_R(16) TF_R(24)
    x0 += k2; x1 += k0 + 2u;
    TF_R(13) TF_R(15) TF_R(26) TF_R(6)
    x0 += k0; x1 += k1 + 3u;
    TF_R(17) TF_R(29) TF_R(16) TF_R(24)
    x0 += k1; x1 += k2 + 4u;
    TF_R(13) TF_R(15) TF_R(26) TF_R(6)
    x0 += k2; x1 += k0 + 5u;
#undef TF_R
    o0 = x0; o1 = x1;
}

__device__ inline float uniform01(unsigned k0, unsigned k1, unsigned idx){
    unsigned a, b;
    tf2x32(k0, k1, 0u, idx, a, b);
    unsigned bits = a ^ b;
    unsigned fb = (bits >> 9) | 0x3F800000u;
    float f = __fadd_rn(__uint_as_float(fb), -1.0f);
    return fmaxf(0.0f, f);
}

/* ---------------- XLA:CPU math replicas (llvm_ir_runtime / Cephes) ---------------- */
__device__ inline float xla_expf(float x){
    float cx = fminf(fmaxf(x, -88.3762626647949f), 88.3762626647950f);
    float fx = floorf(fmaf(cx, 1.44269504088896341f, 0.5f));
    float r = fmaf(-0.693359375f, fx, cx);
    r = fmaf(2.12194440e-4f, fx, r);
    float z = __fmul_rn(r, r);
    float y = 1.9875691500e-4f;
    y = fmaf(y, r, 1.3981999507e-3f);
    y = fmaf(y, r, 8.3334519073e-3f);
    y = fmaf(y, r, 4.1665795894e-2f);
    y = fmaf(y, r, 1.6666665459e-1f);
    y = fmaf(y, r, 5.0000001201e-1f);
    y = fmaf(y, z, r);
    y = __fadd_rn(1.0f, y);
    int n = (int)fx;
    float s = __uint_as_float((unsigned)((n + 127) << 23));
    return __fmul_rn(y, s);
}

__device__ inline float xla_logf(float u){
    unsigned iu = __float_as_uint(u);
    int e = (int)(iu >> 23) - 126;
    float m = __uint_as_float((iu & 0x007FFFFFu) | 0x3F000000u);
    float x;
    if (m < 0.707106781186547524f){ e -= 1; x = __fadd_rn(__fadd_rn(m, -1.0f), m); }
    else                          { x = __fadd_rn(m, -1.0f); }
    float z = __fmul_rn(x, x);
    float y = 7.0376836292e-2f;
    y = fmaf(y, x, -1.1514610310e-1f);
    y = fmaf(y, x,  1.1676998740e-1f);
    y = fmaf(y, x, -1.2420140846e-1f);
    y = fmaf(y, x,  1.4249322787e-1f);
    y = fmaf(y, x, -1.6668057665e-1f);
    y = fmaf(y, x,  2.0000714765e-1f);
    y = fmaf(y, x, -2.4999993993e-1f);
    y = fmaf(y, x,  3.3333331174e-1f);
    y = __fmul_rn(__fmul_rn(y, x), z);
    float ef = (float)e;
    y = fmaf(ef, -2.12194440e-4f, y);
    y = fmaf(z, -0.5f, y);
    x = __fadd_rn(x, y);
    x = fmaf(ef, 0.693359375f, x);
    return x;
}

__device__ inline float xla_log1pf(float x){
    float large_ = xla_logf(__fadd_rn(x, 1.0f));
    float small_ = __fmul_rn(fmaf(-0.5f, x, 1.0f), x);
    return (fabsf(x) < 1e-4f) ? small_ : large_;
}

__device__ inline float xla_tanhf(float x){
    float cx = fminf(fmaxf(x, -7.90531110763549805f), 7.90531110763549805f);
    float x2 = __fmul_rn(cx, cx);
    float p = fmaf(x2, -2.76076847742355e-16f, 2.00018790482477e-13f);
    p = fmaf(x2, p, -8.60467152213735e-11f);
    p = fmaf(x2, p,  5.12229709037114e-08f);
    p = fmaf(x2, p,  1.48572235717979e-05f);
    p = fmaf(x2, p,  6.37261928875436e-04f);
    p = fmaf(x2, p,  4.89352455891786e-03f);
    p = __fmul_rn(cx, p);
    float q = fmaf(x2, 1.19825839466702e-06f, 1.18534705686654e-04f);
    q = fmaf(x2, q, 2.26843463243900e-03f);
    q = fmaf(x2, q, 4.89352518554385e-03f);
    float r = __fdiv_rn(p, q);
    return (fabsf(x) < 0.0004f) ? x : r;
}

__device__ inline float xla_logistic(float x){
    float t = xla_tanhf(__fmul_rn(0.5f, x));
    return __fadd_rn(0.5f, __fmul_rn(0.5f, t));
}

__device__ inline float wredsum(float v){
    #pragma unroll
    for (int o = 16; o; o >>= 1) v += __shfl_xor_sync(0xffffffffu, v, o);
    return v;
}

/* ---------------- JAX associative_scan (odd-even recursion), exact tree ---------------- */
template<int N>
__device__ inline void ascan_mul(const float* x, float* out){
    if constexpr (N == 1){
        out[0] = x[0];
    } else {
        constexpr int NR = N/2;
        float red[NR], odd[NR];
        #pragma unroll
        for (int i = 0; i < NR; i++) red[i] = __fmul_rn(x[2*i], x[2*i+1]);
        ascan_mul<NR>(red, odd);
        out[0] = x[0];
        #pragma unroll
        for (int i = 1; i < (N+1)/2; i++) out[2*i] = __fmul_rn(odd[i-1], x[2*i]);
        #pragma unroll
        for (int i = 0; i < NR; i++) out[2*i+1] = odd[i];
    }
}

template<int N>
__device__ inline void ascan_add(const float* x, float* out){
    if constexpr (N == 1){
        out[0] = x[0];
    } else {
        constexpr int NR = N/2;
        float red[NR], odd[NR];
        #pragma unroll
        for (int i = 0; i < NR; i++) red[i] = __fadd_rn(x[2*i], x[2*i+1]);
        ascan_add<NR>(red, odd);
        out[0] = x[0];
        #pragma unroll
        for (int i = 1; i < (N+1)/2; i++) out[2*i] = __fadd_rn(odd[i-1], x[2*i]);
        #pragma unroll
        for (int i = 0; i < NR; i++) out[2*i+1] = odd[i];
    }
}

/* ---------------- kernels ---------------- */
__global__ void k_init(){
    g_dminU = 0xFFFFFFFFu;
    g_dmaxU = 0u;
}

__global__ void k_transpose(const float* __restrict__ planes){
    __shared__ float sh[32][33];
    int bp   = blockIdx.y;
    int pos0 = blockIdx.x * 32;
    int tx = threadIdx.x, ty = threadIdx.y;
    sh[ty][tx] = planes[(size_t)(bp*32 + ty)*65536 + pos0 + tx];
    __syncthreads();
    g_tp[((size_t)bp*65536 + pos0 + ty)*32 + tx] = sh[tx][ty];
}

__global__ void k_gencoarse(const float* __restrict__ orig, unsigned kz0, unsigned kz1){
    int t = blockIdx.x * blockDim.x + threadIdx.x;
    if (t >= NPTS) return;
    int ray = t / 48, s = t - ray*48;
    float u = uniform01(kz0, kz1, (unsigned)t);
    const float step = 1.0f/47.0f;
    float lin = __fadd_rn(0.5f, __fmul_rn((float)s, step));
    float d = __fadd_rn(__fadd_rn(lin, __fmul_rn(u, step)), -orig[ray*3+2]);
    g_dep[ray*96 + s] = d;
    unsigned b = __float_as_uint(d);
    unsigned m = (b & 0x80000000u) ? ~b : (b | 0x80000000u);
    atomicMin(&g_dminU, m);
    atomicMax(&g_dmaxU, m);
}

/* per-plane bilinear sample (value F with exact reference op-order) + grad accum */
__device__ inline void plane_acc(int bp, float gx, float gy, int lane,
                                 float &F, float &Dx, float &Dy){
    float px = __fadd_rn(__fmul_rn(__fadd_rn(gx, 1.0f), 128.0f), -0.5f);
    float py = __fadd_rn(__fmul_rn(__fadd_rn(gy, 1.0f), 128.0f), -0.5f);
    float x0f = floorf(px), y0f = floorf(py);
    float wx = __fadd_rn(px, -x0f), wy = __fadd_rn(py, -y0f);
    int x0 = (int)x0f, y0 = (int)y0f;
    float acc = 0.0f;
    #pragma unroll
    for (int j = 0; j < 2; j++){
        #pragma unroll
        for (int i = 0; i < 2; i++){
            int ix = x0 + i, iy = y0 + j;
            float m = (ix >= 0 && ix < 256 && iy >= 0 && iy < 256) ? 1.0f : 0.0f;
            int ic = min(max(ix, 0), 255), jc = min(max(iy, 0), 255);
            float v = g_tp[((size_t)(bp*256 + jc)*256 + ic)*32 + lane];
            float wxi = i ? wx : __fadd_rn(1.0f, -wx);
            float wyj = j ? wy : __fadd_rn(1.0f, -wy);
            float w = __fmul_rn(__fmul_rn(wxi, wyj), m);
            acc = __fadd_rn(acc, __fmul_rn(v, w));
            Dx = __fadd_rn(Dx, __fmul_rn(v, __fmul_rn(m, (i ? wyj : -wyj))));
            Dy = __fadd_rn(Dy, __fmul_rn(v, __fmul_rn(m, (j ? wxi : -wxi))));
        }
    }
    F = acc;
}

/* 2 points per warp; weights vectorized from shared; staging via broadcast LDS */
__global__ void __launch_bounds__(256)
k_model(const float* __restrict__ orig, const float* __restrict__ dirs,
        const float* __restrict__ w1, const float* __restrict__ b1,
        const float* __restrict__ w2, const float* __restrict__ b2,
        const float* __restrict__ betap, float* __restrict__ out, int fine)
{
    __shared__ __align__(16) float w1t[64*36];   /* [out k][c], padded 36 */
    __shared__ __align__(16) float w1r[32*68];   /* [c][k], padded 68     */
    __shared__ __align__(16) float w2t[32*68];   /* [out j][k], padded 68 */
    __shared__ float w2c0[64], w2c32[64];
    __shared__ float b1s[64], b2s[33];
    __shared__ __align__(16) float2 fds[8][32];
    __shared__ __align__(16) float4 hqs[8][64];

    int tid = threadIdx.x;
    for (int i = tid; i < 2048; i += 256){
        int c = i >> 6, k = i & 63;
        float v = w1[i];
        w1r[c*68 + k] = v;
        w1t[k*36 + c] = v;
    }
    for (int i = tid; i < 2112; i += 256){
        int k = i / 33, j = i - k*33;
        float v = w2[i];
        if (j < 32) w2t[j*68 + k] = v;
        if (j == 0) w2c0[k] = v;
        if (j == 32) w2c32[k] = v;
    }
    if (tid < 64) b1s[tid] = b1[tid];
    if (tid < 33) b2s[tid] = b2[tid];
    __syncthreads();

    int lane = tid & 31;
    int wid  = tid >> 5;
    int base = (blockIdx.x * 8 + wid) * 2;   /* 12288 blocks * 8 warps * 2 = NPTS */

    int rayP[2], sP[2], slotP[2], bP[2];
    float cxP[2], cyP[2], czP[2];
    float FdP[2], GXP[2], GYP[2], GZP[2];

    #pragma unroll
    for (int p = 0; p < 2; p++){
        int pt = base + p;
        int ray = pt / 48, s = pt - ray*48;
        rayP[p] = ray; sP[p] = s;
        int slot = ray*96 + s + (fine ? 48 : 0);
        slotP[p] = slot;
        bP[p] = ray >> 11;
        float depth = g_dep[slot];
        float ox = orig[ray*3], oy = orig[ray*3+1], oz = orig[ray*3+2];
        float dx = dirs[ray*3], dy = dirs[ray*3+1], dz = dirs[ray*3+2];
        float cx = __fadd_rn(ox, __fmul_rn(depth, dx));
        float cy = __fadd_rn(oy, __fmul_rn(depth, dy));
        float cz = __fadd_rn(oz, __fmul_rn(depth, dz));
        cxP[p] = cx; cyP[p] = cy; czP[p] = cz;
        float F0, F1, F2, GX = 0.f, GY = 0.f, GZ = 0.f;
        plane_acc(bP[p]*3 + 0, cx, cy, lane, F0, GX, GY);
        plane_acc(bP[p]*3 + 1, cx, cz, lane, F1, GX, GZ);
        plane_acc(bP[p]*3 + 2, cz, cy, lane, F2, GZ, GY);
        FdP[p] = __fdiv_rn(__fadd_rn(__fadd_rn(F0, F1), F2), 3.0f);
        GXP[p] = GX; GYP[p] = GY; GZP[p] = GZ;
    }

    fds[wid][lane] = make_float2(FdP[0], FdP[1]);
    __syncwarp();

    /* layer 1: fma chains from 0 ascending c (bit-exact), 2 points at once */
    float pa0 = 0.f, pb0 = 0.f, pa1 = 0.f, pb1 = 0.f;
    #pragma unroll
    for (int cc = 0; cc < 8; cc++){
        float4 wA = *(const float4*)&w1t[lane*36 + cc*4];
        float4 wB = *(const float4*)&w1t[(lane+32)*36 + cc*4];
        const float2* fp = &fds[wid][cc*4];
        float4 xA = *(const float4*)fp;       /* {F0[c],F1[c],F0[c+1],F1[c+1]} */
        float4 xB = *(const float4*)(fp + 2); /* c+2, c+3 */
        pa0 = fmaf(xA.x, wA.x, pa0); pa1 = fmaf(xA.y, wA.x, pa1);
        pb0 = fmaf(xA.x, wB.x, pb0); pb1 = fmaf(xA.y, wB.x, pb1);
        pa0 = fmaf(xA.z, wA.y, pa0); pa1 = fmaf(xA.w, wA.y, pa1);
        pb0 = fmaf(xA.z, wB.y, pb0); pb1 = fmaf(xA.w, wB.y, pb1);
        pa0 = fmaf(xB.x, wA.z, pa0); pa1 = fmaf(xB.y, wA.z, pa1);
        pb0 = fmaf(xB.x, wB.z, pb0); pb1 = fmaf(xB.y, wB.z, pb1);
        pa0 = fmaf(xB.z, wA.w, pa0); pa1 = fmaf(xB.w, wA.w, pa1);
        pb0 = fmaf(xB.z, wB.w, pb0); pb1 = fmaf(xB.w, wB.w, pb1);
    }
    pa0 = __fadd_rn(pa0, b1s[lane]);      pa1 = __fadd_rn(pa1, b1s[lane]);
    pb0 = __fadd_rn(pb0, b1s[lane + 32]); pb1 = __fadd_rn(pb1, b1s[lane + 32]);

    float ha0 = __fadd_rn(fmaxf(pa0, 0.f), xla_log1pf(xla_expf(-fabsf(pa0))));
    float hb0 = __fadd_rn(fmaxf(pb0, 0.f), xla_log1pf(xla_expf(-fabsf(pb0))));
    float ha1 = __fadd_rn(fmaxf(pa1, 0.f), xla_log1pf(xla_expf(-fabsf(pa1))));
    float hb1 = __fadd_rn(fmaxf(pb1, 0.f), xla_log1pf(xla_expf(-fabsf(pb1))));
    float sa0 = xla_expf(__fadd_rn(pa0, -ha0));
    float sb0 = xla_expf(__fadd_rn(pb0, -hb0));
    float sa1 = xla_expf(__fadd_rn(pa1, -ha1));
    float sb1 = xla_expf(__fadd_rn(pb1, -hb1));

    float w20a = w2c0[lane], w20b = w2c0[lane + 32];
    float qa0 = __fmul_rn(sa0, w20a), qb0 = __fmul_rn(sb0, w20b);
    float qa1 = __fmul_rn(sa1, w20a), qb1 = __fmul_rn(sb1, w20b);

    hqs[wid][lane]      = make_float4(ha0, qa0, ha1, qa1);
    hqs[wid][lane + 32] = make_float4(hb0, qb0, hb1, qb1);
    __syncwarp();

    /* layer 2: o chains exact ascending k (sigma-critical at lane 0) */
    float o0 = 0.f, o1 = 0.f, t0 = 0.f, t1 = 0.f;
    #pragma unroll
    for (int kk = 0; kk < 16; kk++){
        float4 w2v = *(const float4*)&w2t[lane*68 + kk*4];
        float4 w1v = *(const float4*)&w1r[lane*68 + kk*4];
        float4 h0 = hqs[wid][kk*4+0];
        float4 h1 = hqs[wid][kk*4+1];
        float4 h2 = hqs[wid][kk*4+2];
        float4 h3 = hqs[wid][kk*4+3];
        o0 = fmaf(h0.x, w2v.x, o0); o1 = fmaf(h0.z, w2v.x, o1);
        t0 = fmaf(h0.y, w1v.x, t0); t1 = fmaf(h0.w, w1v.x, t1);
        o0 = fmaf(h1.x, w2v.y, o0); o1 = fmaf(h1.z, w2v.y, o1);
        t0 = fmaf(h1.y, w1v.y, t0); t1 = fmaf(h1.w, w1v.y, t1);
        o0 = fmaf(h2.x, w2v.z, o0); o1 = fmaf(h2.z, w2v.z, o1);
        t0 = fmaf(h2.y, w1v.z, t0); t1 = fmaf(h2.w, w1v.z, t1);
        o0 = fmaf(h3.x, w2v.w, o0); o1 = fmaf(h3.z, w2v.w, o1);
        t0 = fmaf(h3.y, w1v.w, t0); t1 = fmaf(h3.w, w1v.w, t1);
    }
    o0 = __fadd_rn(o0, b2s[lane]);
    o1 = __fadd_rn(o1, b2s[lane]);

    float w232a = w2c32[lane], w232b = w2c32[lane + 32];
    float o2_0 = __fadd_rn(wredsum(__fadd_rn(__fmul_rn(ha0, w232a), __fmul_rn(hb0, w232b))), b2s[32]);
    float o2_1 = __fadd_rn(wredsum(__fadd_rn(__fmul_rn(ha1, w232a), __fmul_rn(hb1, w232b))), b2s[32]);

    #pragma unroll
    for (int p = 0; p < 2; p++){
        float o   = p ? o1   : o0;
        float o2  = p ? o2_1 : o2_0;
        float tcc = p ? t1   : t0;
        int slot = slotP[p];
        float gxr = __fmul_rn(wredsum(__fmul_rn(tcc, GXP[p])), (128.0f/3.0f));
        float gyr = __fmul_rn(wredsum(__fmul_rn(tcc, GYP[p])), (128.0f/3.0f));
        float gzr = __fmul_rn(wredsum(__fmul_rn(tcc, GZP[p])), (128.0f/3.0f));
        float sigma = __shfl_sync(0xffffffffu, o, 0);

        if (lane >= 1) g_rgb[(size_t)slot*32 + (lane-1)] = __fadd_rn(__fmul_rn(xla_logistic(o), 1.002f), -0.001f);
        if (lane == 31) g_rgb[(size_t)slot*32 + 31] = __fadd_rn(__fmul_rn(xla_logistic(o2), 1.002f), -0.001f);

        if (lane == 0){
            float beta = betap[0];
            float cx = cxP[p], cy = cyP[p], cz = czP[p];
            float r2 = __fadd_rn(__fadd_rn(__fadd_rn(__fmul_rn(cx,cx), __fmul_rn(cy,cy)), __fmul_rn(cz,cz)), 1e-12f);
            float rs = sqrtf(r2);
            float sdf = __fadd_rn(sigma, __fadd_rn(rs, -0.5f));
            float inv = __fdiv_rn(1.0f, rs);
            float gax = __fadd_rn(gxr, __fmul_rn(cx, inv));
            float gay = __fadd_rn(gyr, __fmul_rn(cy, inv));
            float gaz = __fadd_rn(gzr, __fmul_rn(cz, inv));
            int r = rayP[p] & 2047;
            int m = r*48 + sP[p];
            int pidx = bP[p]*196608 + (fine ? 98304 : 0) + m;
            out[OFF_SDF + pidx] = sdf;
            out[OFF_GC + (size_t)pidx*3 + 0] = gax;
            out[OFF_GC + (size_t)pidx*3 + 1] = gay;
            out[OFF_GC + (size_t)pidx*3 + 2] = gaz;
            float y = __fdiv_rn(-sdf, beta);
            g_dens[slot] = __fdiv_rn(xla_logistic(y), beta);
            float nx = -gax;
            float nrm = fmaxf(sqrtf(__fadd_rn(__fadd_rn(__fmul_rn(nx,nx), __fmul_rn(gay,gay)), __fmul_rn(gaz,gaz))), 1e-12f);
            g_gn[(size_t)slot*3 + 0] = __fdiv_rn(nx, nrm);
            g_gn[(size_t)slot*3 + 1] = __fdiv_rn(gay, nrm);
            g_gn[(size_t)slot*3 + 2] = __fdiv_rn(gaz, nrm);
        }
    }
}

__global__ void k_marchimp(unsigned ku0, unsigned ku1){
    int ray = blockIdx.x * blockDim.x + threadIdx.x;
    if (ray >= NRAY) return;
    int rb = ray*96;
    float z[48], dn[48];
    for (int i = 0; i < 48; i++){ z[i] = g_dep[rb+i]; dn[i] = g_dens[rb+i]; }
    float alpha[47], shifted[48];
    shifted[0] = 1.0f;
    for (int i = 0; i < 47; i++){
        float dm = __fmul_rn(0.5f, __fadd_rn(dn[i], dn[i+1]));
        float dt = __fadd_rn(z[i+1], -z[i]);
        float a = __fadd_rn(1.0f, -xla_expf(-__fmul_rn(dm, dt)));
        alpha[i] = a;
        shifted[i+1] = __fadd_rn(__fadd_rn(1.0f, -a), 1e-10f);
    }
    float cp[48];
    ascan_mul<48>(shifted, cp);
    float w[47];
    for (int i = 0; i < 47; i++) w[i] = __fmul_rn(alpha[i], cp[i]);

    float p[45];
    for (int k = 0; k < 45; k++){
        int i = k + 1;
        float wm0 = fmaxf(w[i-1], w[i]);
        float wm1 = fmaxf(w[i], w[i+1]);
        float wa = __fadd_rn(__fmul_rn(0.5f, __fadd_rn(wm0, wm1)), 0.01f);
        p[k] = __fadd_rn(wa, 1e-5f);
    }
    float sum = 0.0f;
    for (int k = 0; k < 45; k++) sum = __fadd_rn(sum, p[k]);

    float pn[45];
    for (int k = 0; k < 45; k++) pn[k] = __fdiv_rn(p[k], sum);
    float cs[45];
    ascan_add<45>(pn, cs);
    float cdf[46]; cdf[0] = 0.0f;
    for (int k = 0; k < 45; k++) cdf[k+1] = cs[k];

    float zm[47];
    for (int i = 0; i < 47; i++) zm[i] = __fmul_rn(0.5f, __fadd_rn(z[i], z[i+1]));
    for (int j = 0; j < 48; j++){
        float u = uniform01(ku0, ku1, (unsigned)(ray*48 + j));
        int lo = 0, hi = 46;
        while (lo < hi){ int mid = (lo + hi) >> 1; if (cdf[mid] <= u) lo = mid + 1; else hi = mid; }
        int below = lo - 1 > 0 ? lo - 1 : 0;
        int above = lo < 45 ? lo : 45;
        float c0 = cdf[below], c1 = cdf[above];
        float b0 = zm[below], b1 = zm[above];
        float diff = __fadd_rn(c1, -c0);
        float den = (diff < 1e-5f) ? 1.0f : diff;
        float fr = __fdiv_rn(__fadd_rn(u, -c0), den);
        g_dep[rb + 48 + j] = __fadd_rn(b0, __fmul_rn(fr, __fadd_rn(b1, -b0)));
    }
}

__global__ void k_merge(float* __restrict__ out){
    int ray = blockIdx.x * blockDim.x + threadIdx.x;
    if (ray >= NRAY) return;
    int rb = ray*96;
    float zc[48], zf[48]; int fi[48];
    for (int i = 0; i < 48; i++) zc[i] = g_dep[rb + i];
    for (int j = 0; j < 48; j++){ zf[j] = g_dep[rb + 48 + j]; fi[j] = j; }
    for (int j = 1; j < 48; j++){
        float v = zf[j]; int id = fi[j]; int k = j - 1;
        while (k >= 0 && zf[k] > v){ zf[k+1] = zf[k]; fi[k+1] = fi[k]; k--; }
        zf[k+1] = v; fi[k+1] = id;
    }
    float Dm[96]; int od[96];
    {
        int i = 0, j = 0;
        for (int n = 0; n < 96; n++){
            bool tc = (j >= 48) || (i < 48 && zc[i] <= zf[j]);
            if (tc){ Dm[n] = zc[i]; od[n] = i; i++; }
            else   { Dm[n] = zf[j]; od[n] = 48 + fi[j]; j++; }
            g_ord[rb + n] = od[n];
        }
    }
    float alpha[95], shifted[96];
    shifted[0] = 1.0f;
    {
        float dprev = g_dens[rb + od[0]];
        for (int n = 0; n < 95; n++){
            float dnx = g_dens[rb + od[n+1]];
            float dt = __fadd_rn(Dm[n+1], -Dm[n]);
            float dm = __fmul_rn(0.5f, __fadd_rn(dprev, dnx));
            float a = __fadd_rn(1.0f, -xla_expf(-__fmul_rn(dm, dt)));
            alpha[n] = a;
            shifted[n+1] = __fadd_rn(__fadd_rn(1.0f, -a), 1e-10f);
            dprev = dnx;
        }
    }
    float cp[96];
    ascan_mul<96>(shifted, cp);

    float wtot = 0.0f, dsum = 0.0f, s0 = 0.f, s1 = 0.f, s2 = 0.f;
    float gp0 = g_gn[(size_t)(rb+od[0])*3],   gp1 = g_gn[(size_t)(rb+od[0])*3+1],
          gp2 = g_gn[(size_t)(rb+od[0])*3+2];
    for (int n = 0; n < 95; n++){
        int o1 = od[n+1];
        float gq0 = g_gn[(size_t)(rb+o1)*3], gq1 = g_gn[(size_t)(rb+o1)*3+1], gq2 = g_gn[(size_t)(rb+o1)*3+2];
        float wgt = __fmul_rn(alpha[n], cp[n]);
        g_w[(size_t)ray*95 + n] = wgt;
        wtot = __fadd_rn(wtot, wgt);
        dsum = __fadd_rn(dsum, __fmul_rn(wgt, __fmul_rn(0.5f, __fadd_rn(Dm[n], Dm[n+1]))));
        s0 = __fadd_rn(s0, __fmul_rn(wgt, __fmul_rn(0.5f, __fadd_rn(gp0, gq0))));
        s1 = __fadd_rn(s1, __fmul_rn(wgt, __fmul_rn(0.5f, __fadd_rn(gp1, gq1))));
        s2 = __fadd_rn(s2, __fmul_rn(wgt, __fmul_rn(0.5f, __fadd_rn(gp2, gq2))));
        gp0 = gq0; gp1 = gq1; gp2 = gq2;
    }
    float depth = __fdiv_rn(dsum, fmaxf(wtot, 1e-12f));
    unsigned mu = g_dminU; unsigned bu = (mu >> 31) ? (mu ^ 0x80000000u) : ~mu;
    unsigned mx = g_dmaxU; unsigned bx = (mx >> 31) ? (mx ^ 0x80000000u) : ~mx;
    float dmin = __uint_as_float(bu), dmax = __uint_as_float(bx);
    depth = fminf(fmaxf(depth, dmin), dmax);
    out[OFF_DEPTH + ray] = depth;
    out[OFF_WSUM + ray] = wtot;
    out[OFF_GRAD + (size_t)ray*3 + 0] = s0;
    out[OFF_GRAD + (size_t)ray*3 + 1] = s1;
    out[OFF_GRAD + (size_t)ray*3 + 2] = s2;
}

__global__ void k_rgbacc(float* __restrict__ out){
    int lane = threadIdx.x & 31;
    int ray = blockIdx.x * (blockDim.x >> 5) + (threadIdx.x >> 5);
    if (ray >= NRAY) return;
    int rb = ray*96;
    int o0 = g_ord[rb];
    float prev = g_rgb[(size_t)(rb + o0)*32 + lane];
    float acc = 0.0f;
    for (int i = 0; i < 95; i++){
        int oi = g_ord[rb + i + 1];
        float cur = g_rgb[(size_t)(rb + oi)*32 + lane];
        float wgt = g_w[(size_t)ray*95 + i];
        acc = __fadd_rn(acc, __fmul_rn(wgt, __fmul_rn(0.5f, __fadd_rn(prev, cur))));
        prev = cur;
    }
    out[OFF_RGB + (size_t)ray*32 + lane] = __fadd_rn(__fmul_rn(acc, 2.0f), -1.0f);
}

/* ---------------- launch ---------------- */
extern "C" void kernel_launch(void* const* d_in, const int* in_sizes, int n_in,
                              void* d_out, int out_size){
    const float* planes = (const float*)d_in[0];
    const float* orig   = (const float*)d_in[1];
    const float* dirs   = (const float*)d_in[2];
    const float* w1     = (const float*)d_in[3];
    const float* b1     = (const float*)d_in[4];
    const float* w2     = (const float*)d_in[5];
    const float* b2     = (const float*)d_in[6];
    const float* beta   = (const float*)d_in[7];
    float* out = (float*)d_out;

    unsigned kz0, kz1, ku0, ku1;
    tf2x32(0u, 42u, 0u, 0u, kz0, kz1);
    tf2x32(0u, 42u, 0u, 1u, ku0, ku1);

    k_init<<<1, 1>>>();
    k_transpose<<<dim3(2048, 6), dim3(32, 32)>>>(planes);
    k_gencoarse<<<768, 256>>>(orig, kz0, kz1);
    k_model<<<12288, 256>>>(orig, dirs, w1, b1, w2, b2, beta, out, 0);
    k_marchimp<<<128, 32>>>(ku0, ku1);
    k_model<<<12288, 256>>>(orig, dirs, w1, b1, w2, b2, beta, out, 1);
    k_merge<<<128, 32>>>(out);
    k_rgbacc<<<512, 256>>>(out);
}

// round 16
// speedup vs baseline: 1.9536x; 1.1935x over previous
#include <cuda_runtime.h>
#include <cstdint>
#include <math.h>

#define NRAY 4096
#define NPTS 196608   /* NRAY * 48 */

/* output offsets (floats) */
#define OFF_RGB   0
#define OFF_DEPTH 131072
#define OFF_WSUM  135168
#define OFF_GRAD  139264
#define OFF_GC    151552
#define OFF_SDF   1331200

/* scratch */
__device__ float    g_tp  [2*3*256*256*32]; /* [b][p][y][x][c] */
__device__ float    g_dep [NRAY*96];
__device__ float    g_dens[NRAY*96];
__device__ float    g_rgb [NRAY*96*32];
__device__ float    g_gn  [NRAY*96*3];
__device__ float    g_w   [NRAY*95];
__device__ int      g_ord [NRAY*96];
__device__ unsigned g_dminU, g_dmaxU;

/* ---------------- Threefry2x32-20 (JAX partitionable) ---------------- */
__host__ __device__ inline unsigned rotl32(unsigned v, int r){ return (v<<r)|(v>>(32-r)); }

__host__ __device__ inline void tf2x32(unsigned k0, unsigned k1, unsigned x0, unsigned x1,
                                       unsigned &o0, unsigned &o1){
    unsigned k2 = k0 ^ k1 ^ 0x1BD11BDAu;
    x0 += k0; x1 += k1;
#define TF_R(r) { x0 += x1; x1 = rotl32(x1,(r)); x1 ^= x0; }
    TF_R(13) TF_R(15) TF_R(26) TF_R(6)
    x0 += k1; x1 += k2 + 1u;
    TF_R(17) TF_R(29) TF_R(16) TF_R(24)
    x0 += k2; x1 += k0 + 2u;
    TF_R(13) TF_R(15) TF_R(26) TF_R(6)
    x0 += k0; x1 += k1 + 3u;
    TF_R(17) TF_R(29) TF_R(16) TF_R(24)
    x0 += k1; x1 += k2 + 4u;
    TF_R(13) TF_R(15) TF_R(26) TF_R(6)
    x0 += k2; x1 += k0 + 5u;
#undef TF_R
    o0 = x0; o1 = x1;
}

__device__ inline float uniform01(unsigned k0, unsigned k1, unsigned idx){
    unsigned a, b;
    tf2x32(k0, k1, 0u, idx, a, b);
    unsigned bits = a ^ b;
    unsigned fb = (bits >> 9) | 0x3F800000u;
    float f = __fadd_rn(__uint_as_float(fb), -1.0f);
    return fmaxf(0.0f, f);
}

/* ---------------- XLA:CPU math replicas (llvm_ir_runtime / Cephes) ---------------- */
__device__ inline float xla_expf(float x){
    float cx = fminf(fmaxf(x, -88.3762626647949f), 88.3762626647950f);
    float fx = floorf(fmaf(cx, 1.44269504088896341f, 0.5f));
    float r = fmaf(-0.693359375f, fx, cx);
    r = fmaf(2.12194440e-4f, fx, r);
    float z = __fmul_rn(r, r);
    float y = 1.9875691500e-4f;
    y = fmaf(y, r, 1.3981999507e-3f);
    y = fmaf(y, r, 8.3334519073e-3f);
    y = fmaf(y, r, 4.1665795894e-2f);
    y = fmaf(y, r, 1.6666665459e-1f);
    y = fmaf(y, r, 5.0000001201e-1f);
    y = fmaf(y, z, r);
    y = __fadd_rn(1.0f, y);
    int n = (int)fx;
    float s = __uint_as_float((unsigned)((n + 127) << 23));
    return __fmul_rn(y, s);
}

__device__ inline float xla_logf(float u){
    unsigned iu = __float_as_uint(u);
    int e = (int)(iu >> 23) - 126;
    float m = __uint_as_float((iu & 0x007FFFFFu) | 0x3F000000u);
    float x;
    if (m < 0.707106781186547524f){ e -= 1; x = __fadd_rn(__fadd_rn(m, -1.0f), m); }
    else                          { x = __fadd_rn(m, -1.0f); }
    float z = __fmul_rn(x, x);
    float y = 7.0376836292e-2f;
    y = fmaf(y, x, -1.1514610310e-1f);
    y = fmaf(y, x,  1.1676998740e-1f);
    y = fmaf(y, x, -1.2420140846e-1f);
    y = fmaf(y, x,  1.4249322787e-1f);
    y = fmaf(y, x, -1.6668057665e-1f);
    y = fmaf(y, x,  2.0000714765e-1f);
    y = fmaf(y, x, -2.4999993993e-1f);
    y = fmaf(y, x,  3.3333331174e-1f);
    y = __fmul_rn(__fmul_rn(y, x), z);
    float ef = (float)e;
    y = fmaf(ef, -2.12194440e-4f, y);
    y = fmaf(z, -0.5f, y);
    x = __fadd_rn(x, y);
    x = fmaf(ef, 0.693359375f, x);
    return x;
}

__device__ inline float xla_log1pf(float x){
    float large_ = xla_logf(__fadd_rn(x, 1.0f));
    float small_ = __fmul_rn(fmaf(-0.5f, x, 1.0f), x);
    return (fabsf(x) < 1e-4f) ? small_ : large_;
}

__device__ inline float xla_tanhf(float x){
    float cx = fminf(fmaxf(x, -7.90531110763549805f), 7.90531110763549805f);
    float x2 = __fmul_rn(cx, cx);
    float p = fmaf(x2, -2.76076847742355e-16f, 2.00018790482477e-13f);
    p = fmaf(x2, p, -8.60467152213735e-11f);
    p = fmaf(x2, p,  5.12229709037114e-08f);
    p = fmaf(x2, p,  1.48572235717979e-05f);
    p = fmaf(x2, p,  6.37261928875436e-04f);
    p = fmaf(x2, p,  4.89352455891786e-03f);
    p = __fmul_rn(cx, p);
    float q = fmaf(x2, 1.19825839466702e-06f, 1.18534705686654e-04f);
    q = fmaf(x2, q, 2.26843463243900e-03f);
    q = fmaf(x2, q, 4.89352518554385e-03f);
    float r = __fdiv_rn(p, q);
    return (fabsf(x) < 0.0004f) ? x : r;
}

__device__ inline float xla_logistic(float x){
    float t = xla_tanhf(__fmul_rn(0.5f, x));
    return __fadd_rn(0.5f, __fmul_rn(0.5f, t));
}

__device__ inline float wredsum(float v){
    #pragma unroll
    for (int o = 16; o; o >>= 1) v += __shfl_xor_sync(0xffffffffu, v, o);
    return v;
}

/* ---------------- warp-parallel JAX associative_scan (identical odd-even tree) ----------
   L: shared levels buffer (input in L[0..n), levels appended); S: same-layout scan buffer.
   Result in S[0..n). Combine order identical to the recursive template. */
template<bool MUL>
__device__ inline void wscan(float* L, float* S, int n, int lane){
    int offs[8], sizes[8];
    int lvl = 0; offs[0] = 0; sizes[0] = n;
    int s = n, off = 0;
    while (s > 1){
        int sc = s >> 1;
        for (int i = lane; i < sc; i += 32){
            float a = L[off + 2*i], b = L[off + 2*i + 1];
            L[off + s + i] = MUL ? __fmul_rn(a, b) : __fadd_rn(a, b);
        }
        __syncwarp();
        off += s; s = sc; lvl++;
        offs[lvl] = off; sizes[lvl] = s;
    }
    if (lane == 0) S[offs[lvl]] = L[offs[lvl]];
    __syncwarp();
    for (int k = lvl - 1; k >= 0; k--){
        int s2 = sizes[k], off2 = offs[k];
        int sc = sizes[k+1], offc = offs[k+1];
        for (int i = lane; i < (s2 + 1)/2; i += 32){
            if (i == 0) S[off2] = L[off2];
            else S[off2 + 2*i] = MUL ? __fmul_rn(S[offc + i - 1], L[off2 + 2*i])
                                     : __fadd_rn(S[offc + i - 1], L[off2 + 2*i]);
        }
        for (int i = lane; i < sc; i += 32) S[off2 + 2*i + 1] = S[offc + i];
        __syncwarp();
    }
}

/* ---------------- kernels ---------------- */
__global__ void k_init(){
    g_dminU = 0xFFFFFFFFu;
    g_dmaxU = 0u;
}

__global__ void k_transpose(const float* __restrict__ planes){
    __shared__ float sh[32][33];
    int bp   = blockIdx.y;
    int pos0 = blockIdx.x * 32;
    int tx = threadIdx.x, ty = threadIdx.y;
    sh[ty][tx] = planes[(size_t)(bp*32 + ty)*65536 + pos0 + tx];
    __syncthreads();
    g_tp[((size_t)bp*65536 + pos0 + ty)*32 + tx] = sh[tx][ty];
}

__global__ void k_gencoarse(const float* __restrict__ orig, unsigned kz0, unsigned kz1){
    int t = blockIdx.x * blockDim.x + threadIdx.x;
    if (t >= NPTS) return;
    int ray = t / 48, s = t - ray*48;
    float u = uniform01(kz0, kz1, (unsigned)t);
    const float step = 1.0f/47.0f;
    float lin = __fadd_rn(0.5f, __fmul_rn((float)s, step));
    float d = __fadd_rn(__fadd_rn(lin, __fmul_rn(u, step)), -orig[ray*3+2]);
    g_dep[ray*96 + s] = d;
    unsigned b = __float_as_uint(d);
    unsigned m = (b & 0x80000000u) ? ~b : (b | 0x80000000u);
    atomicMin(&g_dminU, m);
    atomicMax(&g_dmaxU, m);
}

/* per-plane bilinear sample (value F with exact reference op-order) + grad accum */
__device__ inline void plane_acc(int bp, float gx, float gy, int lane,
                                 float &F, float &Dx, float &Dy){
    float px = __fadd_rn(__fmul_rn(__fadd_rn(gx, 1.0f), 128.0f), -0.5f);
    float py = __fadd_rn(__fmul_rn(__fadd_rn(gy, 1.0f), 128.0f), -0.5f);
    float x0f = floorf(px), y0f = floorf(py);
    float wx = __fadd_rn(px, -x0f), wy = __fadd_rn(py, -y0f);
    int x0 = (int)x0f, y0 = (int)y0f;
    float acc = 0.0f;
    #pragma unroll
    for (int j = 0; j < 2; j++){
        #pragma unroll
        for (int i = 0; i < 2; i++){
            int ix = x0 + i, iy = y0 + j;
            float m = (ix >= 0 && ix < 256 && iy >= 0 && iy < 256) ? 1.0f : 0.0f;
            int ic = min(max(ix, 0), 255), jc = min(max(iy, 0), 255);
            float v = g_tp[((size_t)(bp*256 + jc)*256 + ic)*32 + lane];
            float wxi = i ? wx : __fadd_rn(1.0f, -wx);
            float wyj = j ? wy : __fadd_rn(1.0f, -wy);
            float w = __fmul_rn(__fmul_rn(wxi, wyj), m);
            acc = __fadd_rn(acc, __fmul_rn(v, w));
            Dx = __fadd_rn(Dx, __fmul_rn(v, __fmul_rn(m, (i ? wyj : -wyj))));
            Dy = __fadd_rn(Dy, __fmul_rn(v, __fmul_rn(m, (j ? wxi : -wxi))));
        }
    }
    F = acc;
}

/* 2 points per warp; weights vectorized from shared; staging via broadcast LDS */
__global__ void __launch_bounds__(256)
k_model(const float* __restrict__ orig, const float* __restrict__ dirs,
        const float* __restrict__ w1, const float* __restrict__ b1,
        const float* __restrict__ w2, const float* __restrict__ b2,
        const float* __restrict__ betap, float* __restrict__ out, int fine)
{
    __shared__ __align__(16) float w1t[64*36];   /* [out k][c], padded 36 */
    __shared__ __align__(16) float w1r[32*68];   /* [c][k], padded 68     */
    __shared__ __align__(16) float w2t[32*68];   /* [out j][k], padded 68 */
    __shared__ float w2c0[64], w2c32[64];
    __shared__ float b1s[64], b2s[33];
    __shared__ __align__(16) float2 fds[8][32];
    __shared__ __align__(16) float4 hqs[8][64];

    int tid = threadIdx.x;
    for (int i = tid; i < 2048; i += 256){
        int c = i >> 6, k = i & 63;
        float v = w1[i];
        w1r[c*68 + k] = v;
        w1t[k*36 + c] = v;
    }
    for (int i = tid; i < 2112; i += 256){
        int k = i / 33, j = i - k*33;
        float v = w2[i];
        if (j < 32) w2t[j*68 + k] = v;
        if (j == 0) w2c0[k] = v;
        if (j == 32) w2c32[k] = v;
    }
    if (tid < 64) b1s[tid] = b1[tid];
    if (tid < 33) b2s[tid] = b2[tid];
    __syncthreads();

    int lane = tid & 31;
    int wid  = tid >> 5;
    int base = (blockIdx.x * 8 + wid) * 2;

    int rayP[2], sP[2], slotP[2], bP[2];
    float cxP[2], cyP[2], czP[2];
    float FdP[2], GXP[2], GYP[2], GZP[2];

    #pragma unroll
    for (int p = 0; p < 2; p++){
        int pt = base + p;
        int ray = pt / 48, s = pt - ray*48;
        rayP[p] = ray; sP[p] = s;
        int slot = ray*96 + s + (fine ? 48 : 0);
        slotP[p] = slot;
        bP[p] = ray >> 11;
        float depth = g_dep[slot];
        float ox = orig[ray*3], oy = orig[ray*3+1], oz = orig[ray*3+2];
        float dx = dirs[ray*3], dy = dirs[ray*3+1], dz = dirs[ray*3+2];
        float cx = __fadd_rn(ox, __fmul_rn(depth, dx));
        float cy = __fadd_rn(oy, __fmul_rn(depth, dy));
        float cz = __fadd_rn(oz, __fmul_rn(depth, dz));
        cxP[p] = cx; cyP[p] = cy; czP[p] = cz;
        float F0, F1, F2, GX = 0.f, GY = 0.f, GZ = 0.f;
        plane_acc(bP[p]*3 + 0, cx, cy, lane, F0, GX, GY);
        plane_acc(bP[p]*3 + 1, cx, cz, lane, F1, GX, GZ);
        plane_acc(bP[p]*3 + 2, cz, cy, lane, F2, GZ, GY);
        FdP[p] = __fdiv_rn(__fadd_rn(__fadd_rn(F0, F1), F2), 3.0f);
        GXP[p] = GX; GYP[p] = GY; GZP[p] = GZ;
    }

    fds[wid][lane] = make_float2(FdP[0], FdP[1]);
    __syncwarp();

    float pa0 = 0.f, pb0 = 0.f, pa1 = 0.f, pb1 = 0.f;
    #pragma unroll
    for (int cc = 0; cc < 8; cc++){
        float4 wA = *(const float4*)&w1t[lane*36 + cc*4];
        float4 wB = *(const float4*)&w1t[(lane+32)*36 + cc*4];
        const float2* fp = &fds[wid][cc*4];
        float4 xA = *(const float4*)fp;
        float4 xB = *(const float4*)(fp + 2);
        pa0 = fmaf(xA.x, wA.x, pa0); pa1 = fmaf(xA.y, wA.x, pa1);
        pb0 = fmaf(xA.x, wB.x, pb0); pb1 = fmaf(xA.y, wB.x, pb1);
        pa0 = fmaf(xA.z, wA.y, pa0); pa1 = fmaf(xA.w, wA.y, pa1);
        pb0 = fmaf(xA.z, wB.y, pb0); pb1 = fmaf(xA.w, wB.y, pb1);
        pa0 = fmaf(xB.x, wA.z, pa0); pa1 = fmaf(xB.y, wA.z, pa1);
        pb0 = fmaf(xB.x, wB.z, pb0); pb1 = fmaf(xB.y, wB.z, pb1);
        pa0 = fmaf(xB.z, wA.w, pa0); pa1 = fmaf(xB.w, wA.w, pa1);
        pb0 = fmaf(xB.z, wB.w, pb0); pb1 = fmaf(xB.w, wB.w, pb1);
    }
    pa0 = __fadd_rn(pa0, b1s[lane]);      pa1 = __fadd_rn(pa1, b1s[lane]);
    pb0 = __fadd_rn(pb0, b1s[lane + 32]); pb1 = __fadd_rn(pb1, b1s[lane + 32]);

    float ha0 = __fadd_rn(fmaxf(pa0, 0.f), xla_log1pf(xla_expf(-fabsf(pa0))));
    float hb0 = __fadd_rn(fmaxf(pb0, 0.f), xla_log1pf(xla_expf(-fabsf(pb0))));
    float ha1 = __fadd_rn(fmaxf(pa1, 0.f), xla_log1pf(xla_expf(-fabsf(pa1))));
    float hb1 = __fadd_rn(fmaxf(pb1, 0.f), xla_log1pf(xla_expf(-fabsf(pb1))));
    float sa0 = xla_expf(__fadd_rn(pa0, -ha0));
    float sb0 = xla_expf(__fadd_rn(pb0, -hb0));
    float sa1 = xla_expf(__fadd_rn(pa1, -ha1));
    float sb1 = xla_expf(__fadd_rn(pb1, -hb1));

    float w20a = w2c0[lane], w20b = w2c0[lane + 32];
    float qa0 = __fmul_rn(sa0, w20a), qb0 = __fmul_rn(sb0, w20b);
    float qa1 = __fmul_rn(sa1, w20a), qb1 = __fmul_rn(sb1, w20b);

    hqs[wid][lane]      = make_float4(ha0, qa0, ha1, qa1);
    hqs[wid][lane + 32] = make_float4(hb0, qb0, hb1, qb1);
    __syncwarp();

    float o0 = 0.f, o1 = 0.f, t0 = 0.f, t1 = 0.f;
    #pragma unroll
    for (int kk = 0; kk < 16; kk++){
        float4 w2v = *(const float4*)&w2t[lane*68 + kk*4];
        float4 w1v = *(const float4*)&w1r[lane*68 + kk*4];
        float4 h0 = hqs[wid][kk*4+0];
        float4 h1 = hqs[wid][kk*4+1];
        float4 h2 = hqs[wid][kk*4+2];
        float4 h3 = hqs[wid][kk*4+3];
        o0 = fmaf(h0.x, w2v.x, o0); o1 = fmaf(h0.z, w2v.x, o1);
        t0 = fmaf(h0.y, w1v.x, t0); t1 = fmaf(h0.w, w1v.x, t1);
        o0 = fmaf(h1.x, w2v.y, o0); o1 = fmaf(h1.z, w2v.y, o1);
        t0 = fmaf(h1.y, w1v.y, t0); t1 = fmaf(h1.w, w1v.y, t1);
        o0 = fmaf(h2.x, w2v.z, o0); o1 = fmaf(h2.z, w2v.z, o1);
        t0 = fmaf(h2.y, w1v.z, t0); t1 = fmaf(h2.w, w1v.z, t1);
        o0 = fmaf(h3.x, w2v.w, o0); o1 = fmaf(h3.z, w2v.w, o1);
        t0 = fmaf(h3.y, w1v.w, t0); t1 = fmaf(h3.w, w1v.w, t1);
    }
    o0 = __fadd_rn(o0, b2s[lane]);
    o1 = __fadd_rn(o1, b2s[lane]);

    float w232a = w2c32[lane], w232b = w2c32[lane + 32];
    float o2_0 = __fadd_rn(wredsum(__fadd_rn(__fmul_rn(ha0, w232a), __fmul_rn(hb0, w232b))), b2s[32]);
    float o2_1 = __fadd_rn(wredsum(__fadd_rn(__fmul_rn(ha1, w232a), __fmul_rn(hb1, w232b))), b2s[32]);

    #pragma unroll
    for (int p = 0; p < 2; p++){
        float o   = p ? o1   : o0;
        float o2  = p ? o2_1 : o2_0;
        float tcc = p ? t1   : t0;
        int slot = slotP[p];
        float gxr = __fmul_rn(wredsum(__fmul_rn(tcc, GXP[p])), (128.0f/3.0f));
        float gyr = __fmul_rn(wredsum(__fmul_rn(tcc, GYP[p])), (128.0f/3.0f));
        float gzr = __fmul_rn(wredsum(__fmul_rn(tcc, GZP[p])), (128.0f/3.0f));
        float sigma = __shfl_sync(0xffffffffu, o, 0);

        if (lane >= 1) g_rgb[(size_t)slot*32 + (lane-1)] = __fadd_rn(__fmul_rn(xla_logistic(o), 1.002f), -0.001f);
        if (lane == 31) g_rgb[(size_t)slot*32 + 31] = __fadd_rn(__fmul_rn(xla_logistic(o2), 1.002f), -0.001f);

        if (lane == 0){
            float beta = betap[0];
            float cx = cxP[p], cy = cyP[p], cz = czP[p];
            float r2 = __fadd_rn(__fadd_rn(__fadd_rn(__fmul_rn(cx,cx), __fmul_rn(cy,cy)), __fmul_rn(cz,cz)), 1e-12f);
            float rs = sqrtf(r2);
            float sdf = __fadd_rn(sigma, __fadd_rn(rs, -0.5f));
            float inv = __fdiv_rn(1.0f, rs);
            float gax = __fadd_rn(gxr, __fmul_rn(cx, inv));
            float gay = __fadd_rn(gyr, __fmul_rn(cy, inv));
            float gaz = __fadd_rn(gzr, __fmul_rn(cz, inv));
            int r = rayP[p] & 2047;
            int m = r*48 + sP[p];
            int pidx = bP[p]*196608 + (fine ? 98304 : 0) + m;
            out[OFF_SDF + pidx] = sdf;
            out[OFF_GC + (size_t)pidx*3 + 0] = gax;
            out[OFF_GC + (size_t)pidx*3 + 1] = gay;
            out[OFF_GC + (size_t)pidx*3 + 2] = gaz;
            float y = __fdiv_rn(-sdf, beta);
            g_dens[slot] = __fdiv_rn(xla_logistic(y), beta);
            float nx = -gax;
            float nrm = fmaxf(sqrtf(__fadd_rn(__fadd_rn(__fmul_rn(nx,nx), __fmul_rn(gay,gay)), __fmul_rn(gaz,gaz))), 1e-12f);
            g_gn[(size_t)slot*3 + 0] = __fdiv_rn(nx, nrm);
            g_gn[(size_t)slot*3 + 1] = __fdiv_rn(gay, nrm);
            g_gn[(size_t)slot*3 + 2] = __fdiv_rn(gaz, nrm);
        }
    }
}

/* warp-per-ray importance sampling. Buffer layout (per warp, 656 floats):
   z=0(48) w=48(48: first dn, then reused for w) alpha=96(47) L=143(94) S=237(94)
   p=331(45) Lp=376(86) Sp=462(86) cdf=548(46) zm=594(47) sum=641 */
__global__ void __launch_bounds__(256) k_marchimp(unsigned ku0, unsigned ku1){
    __shared__ float ws[8][656];
    int lane = threadIdx.x & 31, wid = threadIdx.x >> 5;
    int ray = blockIdx.x * 8 + wid;
    if (ray >= NRAY) return;
    float* z     = ws[wid];
    float* dnw   = z + 48;
    float* alpha = dnw + 48;
    float* L     = alpha + 47;
    float* S     = L + 94;
    float* p     = S + 94;
    float* Lp    = p + 45;
    float* Sp    = Lp + 86;
    float* cdf   = Sp + 86;
    float* zm    = cdf + 46;
    float* sump  = zm + 47;
    int rb = ray*96;

    for (int i = lane; i < 48; i += 32){ z[i] = g_dep[rb+i]; dnw[i] = g_dens[rb+i]; }
    __syncwarp();
    for (int i = lane; i < 47; i += 32){
        float dm = __fmul_rn(0.5f, __fadd_rn(dnw[i], dnw[i+1]));
        float dt = __fadd_rn(z[i+1], -z[i]);
        float a = __fadd_rn(1.0f, -xla_expf(-__fmul_rn(dm, dt)));
        alpha[i] = a;
        L[i+1] = __fadd_rn(__fadd_rn(1.0f, -a), 1e-10f);
    }
    if (lane == 0) L[0] = 1.0f;
    __syncwarp();
    wscan<true>(L, S, 48, lane);
    for (int i = lane; i < 47; i += 32) dnw[i] = __fmul_rn(alpha[i], S[i]);  /* w */
    __syncwarp();
    for (int k = lane; k < 45; k += 32){
        float wm0 = fmaxf(dnw[k],   dnw[k+1]);
        float wm1 = fmaxf(dnw[k+1], dnw[k+2]);
        float wa = __fadd_rn(__fmul_rn(0.5f, __fadd_rn(wm0, wm1)), 0.01f);
        p[k] = __fadd_rn(wa, 1e-5f);
    }
    __syncwarp();
    if (lane == 0){
        float sum = 0.0f;
        for (int k = 0; k < 45; k++) sum = __fadd_rn(sum, p[k]);   /* CPU reduce order */
        sump[0] = sum;
    }
    __syncwarp();
    float sum = sump[0];
    for (int k = lane; k < 45; k += 32) Lp[k] = __fdiv_rn(p[k], sum);
    __syncwarp();
    wscan<false>(Lp, Sp, 45, lane);
    if (lane == 0) cdf[0] = 0.0f;
    for (int k = lane; k < 45; k += 32) cdf[k+1] = Sp[k];
    for (int i = lane; i < 47; i += 32) zm[i] = __fmul_rn(0.5f, __fadd_rn(z[i], z[i+1]));
    __syncwarp();
    for (int j = lane; j < 48; j += 32){
        float u = uniform01(ku0, ku1, (unsigned)(ray*48 + j));
        int lo = 0, hi = 46;
        while (lo < hi){ int mid = (lo + hi) >> 1; if (cdf[mid] <= u) lo = mid + 1; else hi = mid; }
        int below = lo - 1 > 0 ? lo - 1 : 0;
        int above = lo < 45 ? lo : 45;
        float c0 = cdf[below], c1 = cdf[above];
        float b0 = zm[below], b1 = zm[above];
        float diff = __fadd_rn(c1, -c0);
        float den = (diff < 1e-5f) ? 1.0f : diff;
        float fr = __fdiv_rn(__fadd_rn(u, -c0), den);
        g_dep[rb + 48 + j] = __fadd_rn(b0, __fmul_rn(fr, __fadd_rn(b1, -b0)));
    }
}

/* warp-per-ray merge. Layout (per warp, 1152 floats):
   sd=0(96) Dm=96(96) dens=192(96) alpha=288(95) wgt=383(95) L=478(190) S=668(190) gq=858(288) */
__global__ void __launch_bounds__(256) k_merge(float* __restrict__ out){
    __shared__ float ws[8][1152];
    __shared__ int   ods[8][96];
    int lane = threadIdx.x & 31, wid = threadIdx.x >> 5;
    int ray = blockIdx.x * 8 + wid;
    if (ray >= NRAY) return;
    float* sd    = ws[wid];
    float* Dm    = sd + 96;
    float* dens  = Dm + 96;
    float* alpha = dens + 96;
    float* wgt   = alpha + 95;
    float* L     = wgt + 95;
    float* S     = L + 190;
    float* gq    = S + 190;     /* [c*96 + n] */
    int* od = ods[wid];
    int rb = ray*96;

    for (int i = lane; i < 96; i += 32) sd[i] = g_dep[rb + i];
    __syncwarp();

    /* stable rank-sort of concat depths (coarse indices 0..47 precede fine on ties) */
    float myd[3]; int myr[3];
    #pragma unroll
    for (int t = 0; t < 3; t++){ myd[t] = sd[lane + t*32]; myr[t] = 0; }
    for (int j = 0; j < 96; j++){
        float dj = sd[j];
        #pragma unroll
        for (int t = 0; t < 3; t++){
            int e = lane + t*32;
            myr[t] += (dj < myd[t]) || (dj == myd[t] && j < e);
        }
    }
    #pragma unroll
    for (int t = 0; t < 3; t++){
        int e = lane + t*32;
        od[myr[t]] = e;
        Dm[myr[t]] = myd[t];
    }
    __syncwarp();
    for (int n = lane; n < 96; n += 32){
        int e = od[n];
        g_ord[rb + n] = e;
        dens[n] = g_dens[rb + e];
        size_t gb = (size_t)(rb + e)*3;
        gq[n]       = g_gn[gb];
        gq[96 + n]  = g_gn[gb + 1];
        gq[192 + n] = g_gn[gb + 2];
    }
    __syncwarp();
    for (int n = lane; n < 95; n += 32){
        float dt = __fadd_rn(Dm[n+1], -Dm[n]);
        float dm = __fmul_rn(0.5f, __fadd_rn(dens[n], dens[n+1]));
        float a = __fadd_rn(1.0f, -xla_expf(-__fmul_rn(dm, dt)));
        alpha[n] = a;
        L[n+1] = __fadd_rn(__fadd_rn(1.0f, -a), 1e-10f);
    }
    if (lane == 0) L[0] = 1.0f;
    __syncwarp();
    wscan<true>(L, S, 96, lane);
    for (int n = lane; n < 95; n += 32){
        float wg = __fmul_rn(alpha[n], S[n]);   /* exact weights */
        wgt[n] = wg;
        g_w[(size_t)ray*95 + n] = wg;
    }
    __syncwarp();

    /* smooth reductions: tree order OK */
    float pw = 0.f, pd = 0.f, p0 = 0.f, p1 = 0.f, p2 = 0.f;
    for (int n = lane; n < 95; n += 32){
        float wg = wgt[n];
        pw += wg;
        pd = fmaf(wg, 0.5f*(Dm[n] + Dm[n+1]), pd);
        p0 = fmaf(wg, 0.5f*(gq[n]       + gq[n+1]),       p0);
        p1 = fmaf(wg, 0.5f*(gq[96+n]    + gq[96+n+1]),    p1);
        p2 = fmaf(wg, 0.5f*(gq[192+n]   + gq[192+n+1]),   p2);
    }
    pw = wredsum(pw); pd = wredsum(pd);
    p0 = wredsum(p0); p1 = wredsum(p1); p2 = wredsum(p2);

    if (lane == 0){
        float depth = __fdiv_rn(pd, fmaxf(pw, 1e-12f));
        unsigned mu = g_dminU; unsigned bu = (mu >> 31) ? (mu ^ 0x80000000u) : ~mu;
        unsigned mx = g_dmaxU; unsigned bx = (mx >> 31) ? (mx ^ 0x80000000u) : ~mx;
        float dmin = __uint_as_float(bu), dmax = __uint_as_float(bx);
        depth = fminf(fmaxf(depth, dmin), dmax);
        out[OFF_DEPTH + ray] = depth;
        out[OFF_WSUM + ray] = pw;
        out[OFF_GRAD + (size_t)ray*3 + 0] = p0;
        out[OFF_GRAD + (size_t)ray*3 + 1] = p1;
        out[OFF_GRAD + (size_t)ray*3 + 2] = p2;
    }
}

__global__ void k_rgbacc(float* __restrict__ out){
    int lane = threadIdx.x & 31;
    int ray = blockIdx.x * (blockDim.x >> 5) + (threadIdx.x >> 5);
    if (ray >= NRAY) return;
    int rb = ray*96;
    int o0 = g_ord[rb];
    float prev = g_rgb[(size_t)(rb + o0)*32 + lane];
    float acc = 0.0f;
    for (int i = 0; i < 95; i++){
        int oi = g_ord[rb + i + 1];
        float cur = g_rgb[(size_t)(rb + oi)*32 + lane];
        float wgt = g_w[(size_t)ray*95 + i];
        acc = __fadd_rn(acc, __fmul_rn(wgt, __fmul_rn(0.5f, __fadd_rn(prev, cur))));
        prev = cur;
    }
    out[OFF_RGB + (size_t)ray*32 + lane] = __fadd_rn(__fmul_rn(acc, 2.0f), -1.0f);
}

/* ---------------- launch ---------------- */
extern "C" void kernel_launch(void* const* d_in, const int* in_sizes, int n_in,
                              void* d_out, int out_size){
    const float* planes = (const float*)d_in[0];
    const float* orig   = (const float*)d_in[1];
    const float* dirs   = (const float*)d_in[2];
    const float* w1     = (const float*)d_in[3];
    const float* b1     = (const float*)d_in[4];
    const float* w2     = (const float*)d_in[5];
    const float* b2     = (const float*)d_in[6];
    const float* beta   = (const float*)d_in[7];
    float* out = (float*)d_out;

    unsigned kz0, kz1, ku0, ku1;
    tf2x32(0u, 42u, 0u, 0u, kz0, kz1);
    tf2x32(0u, 42u, 0u, 1u, ku0, ku1);

    k_init<<<1, 1>>>();
    k_transpose<<<dim3(2048, 6), dim3(32, 32)>>>(planes);
    k_gencoarse<<<768, 256>>>(orig, kz0, kz1);
    k_model<<<12288, 256>>>(orig, dirs, w1, b1, w2, b2, beta, out, 0);
    k_marchimp<<<512, 256>>>(ku0, ku1);
    k_model<<<12288, 256>>>(orig, dirs, w1, b1, w2, b2, beta, out, 1);
    k_merge<<<512, 256>>>(out);
    k_rgbacc<<<512, 256>>>(out);
}